// round 1
// baseline (speedup 1.0000x reference)
#include <cuda_runtime.h>
#include <cuda_bf16.h>
#include <math.h>

// ---------------------------------------------------------------------------
// Static device scratch (no allocations allowed)
// ---------------------------------------------------------------------------
__device__ float d_out0[2*64*8*3000];          // stage0 pre-BN output [b][o][h][w]
__device__ float d_h1[2*4*1500*64];            // stage1 input, position-major [b][h][w][c]
__device__ float d_qkv1[2*6*1504*768];         // stage1 q|k|v on padded grid, [p][768]
__device__ float d_out1[2*4*1500*128];         // stage1 pre-BN output, position-major
__device__ float d_h2[2*2*750*128];            // stage2 input, position-major
__device__ float d_qkv2[2*2*754*96];           // stage2 q|k|v on padded grid, [p][96]
__device__ float d_out2[2*750*16];             // stage2 pre-BN output, position-major

__device__ float d_Wcat1[64*768];              // stage1 fused weights
__device__ float d_Wcat2[128*96];              // stage2 fused weights
__device__ float d_Weff0[5*64];                // stage0 folded mixture value weights
__device__ float d_emb1[4*10];                 // stage1 mixture softmax [m][kl]
__device__ float d_emb2[4*10];                 // stage2 mixture softmax [m][kl]
__device__ float d_C0;                         // dot(p0_q, p0_k)

__device__ float d_scale0[64], d_shift0[64];
__device__ float d_scale1[128], d_shift1[128];
__device__ float d_scale2[16], d_shift2[16];
__device__ float d_sum1[128], d_sumsq1[128];

// ---------------------------------------------------------------------------
// K0: precompute mixture embeddings, folded weights, zero accumulators
// ---------------------------------------------------------------------------
__global__ void k0_pre(const float* p0_q, const float* p0_k, const float* p0_v,
                       const float* p0_ea, const float* p0_eb, const float* p0_em,
                       const float* p1_q, const float* p1_k, const float* p1_v,
                       const float* p1_ea, const float* p1_eb, const float* p1_em,
                       const float* p2_q, const float* p2_k, const float* p2_v,
                       const float* p2_ea, const float* p2_eb, const float* p2_em)
{
    int t = threadIdx.x;
    __shared__ float logit0[4][5], logit1[4][10], logit2[4][10];
    __shared__ float emb0s[4][5];

    if (t == 0) {
        float s = 0.f;
        for (int o = 0; o < 64; o++) s += p0_q[o] * p0_k[o];
        d_C0 = s;
    }
    // stage0 logits: kh=1, kw=5 ; ea [64][1], eb [64][5], em [4][64]
    if (t >= 128 && t < 148) {
        int u = t - 128; int m = u / 5, j = u % 5;
        float la = 0.f, lb = 0.f;
        for (int o = 0; o < 64; o++) {
            la += p0_em[m*64+o] * p0_ea[o];
            lb += p0_em[m*64+o] * p0_eb[o*5+j];
        }
        logit0[m][j] = la + lb;
    }
    // stage1 logits: kh=2, kw=5 ; ea [128][2], eb [128][5], em [4][128]
    if (t < 40) {
        int m = t / 10, kl = t % 10, i = kl / 5, j = kl % 5;
        float la = 0.f, lb = 0.f;
        for (int o = 0; o < 128; o++) {
            la += p1_em[m*128+o] * p1_ea[o*2+i];
            lb += p1_em[m*128+o] * p1_eb[o*5+j];
        }
        logit1[m][kl] = la + lb;
    }
    // stage2 logits: kh=2, kw=5 ; ea [16][2], eb [16][5], em [4][16]
    if (t >= 64 && t < 104) {
        int u = t - 64; int m = u / 10, kl = u % 10, i = kl / 5, j = kl % 5;
        float la = 0.f, lb = 0.f;
        for (int o = 0; o < 16; o++) {
            la += p2_em[m*16+o] * p2_ea[o*2+i];
            lb += p2_em[m*16+o] * p2_eb[o*5+j];
        }
        logit2[m][kl] = la + lb;
    }
    __syncthreads();
    // softmax over mixtures (axis m)
    if (t < 5) {
        float mx = -1e30f;
        for (int m = 0; m < 4; m++) mx = fmaxf(mx, logit0[m][t]);
        float e[4], s = 0.f;
        for (int m = 0; m < 4; m++) { e[m] = __expf(logit0[m][t]-mx); s += e[m]; }
        for (int m = 0; m < 4; m++) emb0s[m][t] = e[m] / s;
    }
    if (t >= 32 && t < 42) {
        int kl = t - 32;
        float mx = -1e30f;
        for (int m = 0; m < 4; m++) mx = fmaxf(mx, logit1[m][kl]);
        float e[4], s = 0.f;
        for (int m = 0; m < 4; m++) { e[m] = __expf(logit1[m][kl]-mx); s += e[m]; }
        for (int m = 0; m < 4; m++) d_emb1[m*10+kl] = e[m] / s;
    }
    if (t >= 64 && t < 74) {
        int kl = t - 64;
        float mx = -1e30f;
        for (int m = 0; m < 4; m++) mx = fmaxf(mx, logit2[m][kl]);
        float e[4], s = 0.f;
        for (int m = 0; m < 4; m++) { e[m] = __expf(logit2[m][kl]-mx); s += e[m]; }
        for (int m = 0; m < 4; m++) d_emb2[m*10+kl] = e[m] / s;
    }
    __syncthreads();
    // Weff0[l][o] = sum_m emb0[m][l] * p0_v[m][0][o]
    for (int idx = t; idx < 5*64; idx += blockDim.x) {
        int l = idx / 64, o = idx % 64;
        float s = 0.f;
        for (int m = 0; m < 4; m++) s += emb0s[m][l] * p0_v[m*64+o];
        d_Weff0[idx] = s;
    }
    // Wcat1 [64][768] = q(128) | k(128) | v(m=0..3,128)
    for (int idx = t; idx < 64*768; idx += blockDim.x) {
        int c = idx / 768, j = idx % 768;
        float v;
        if (j < 128)       v = p1_q[c*128 + j];
        else if (j < 256)  v = p1_k[c*128 + (j-128)];
        else { int m = (j-256) >> 7, o = (j-256) & 127; v = p1_v[(m*64+c)*128 + o]; }
        d_Wcat1[idx] = v;
    }
    // Wcat2 [128][96] = q(16) | k(16) | v(m=0..3,16)
    for (int idx = t; idx < 128*96; idx += blockDim.x) {
        int c = idx / 96, j = idx % 96;
        float v;
        if (j < 16)       v = p2_q[c*16 + j];
        else if (j < 32)  v = p2_k[c*16 + (j-16)];
        else { int m = (j-32) >> 4, o = (j-32) & 15; v = p2_v[(m*128+c)*16 + o]; }
        d_Wcat2[idx] = v;
    }
    if (t < 128) { d_sum1[t] = 0.f; d_sumsq1[t] = 0.f; }
}

// ---------------------------------------------------------------------------
// K1: stage0 attention (Cin=1 collapses scores to scalars)
// grid (24, 8, 2), block 128
// ---------------------------------------------------------------------------
__global__ void k1_stem0(const float* x)
{
    __shared__ float wsh[5*64];
    for (int i = threadIdx.x; i < 320; i += 128) wsh[i] = d_Weff0[i];
    __syncthreads();

    int w = blockIdx.x * 128 + threadIdx.x;
    int h = blockIdx.y, b = blockIdx.z;
    if (w >= 3000) return;

    const float* xr = x + (b*8 + h) * 3000;
    float xc = xr[w];
    float C0 = d_C0;
    float xl[5], sc[5];
    float mx = -1e30f;
    #pragma unroll
    for (int l = 0; l < 5; l++) {
        int c = w + l - 2;
        xl[l] = (c >= 0 && c < 3000) ? xr[c] : 0.f;
        sc[l] = xc * xl[l] * C0;
        mx = fmaxf(mx, sc[l]);
    }
    float s = 0.f;
    #pragma unroll
    for (int l = 0; l < 5; l++) { sc[l] = __expf(sc[l]-mx); s += sc[l]; }
    float inv = 1.f / s;
    float g[5];
    #pragma unroll
    for (int l = 0; l < 5; l++) g[l] = sc[l] * inv * xl[l];

    float* outp = d_out0 + (size_t)b*1536000 + h*3000 + w;
    for (int o = 0; o < 64; o++) {
        float acc = 0.f;
        #pragma unroll
        for (int l = 0; l < 5; l++) acc += g[l] * wsh[l*64 + o];
        outp[o*24000] = acc;
    }
}

// ---------------------------------------------------------------------------
// K2: stage0 BN stats (one block per channel)
// ---------------------------------------------------------------------------
__global__ void k2_bn0(const float* g, const float* bb)
{
    int o = blockIdx.x;
    const float* base = d_out0 + o * 24000;
    float s = 0.f, s2 = 0.f;
    for (int i = threadIdx.x; i < 24000; i += blockDim.x) {
        float v0 = base[i];
        float v1 = base[1536000 + i];
        s += v0 + v1; s2 += v0*v0 + v1*v1;
    }
    __shared__ float sh[256], sh2[256];
    sh[threadIdx.x] = s; sh2[threadIdx.x] = s2;
    __syncthreads();
    for (int st = 128; st > 0; st >>= 1) {
        if (threadIdx.x < st) { sh[threadIdx.x] += sh[threadIdx.x+st]; sh2[threadIdx.x] += sh2[threadIdx.x+st]; }
        __syncthreads();
    }
    if (threadIdx.x == 0) {
        float n = 48000.f;
        float mean = sh[0] / n;
        float var  = sh2[0] / n - mean*mean;
        float sc = g[o] * rsqrtf(var + 1e-5f);
        d_scale0[o] = sc;
        d_shift0[o] = bb[o] - mean * sc;
    }
}

// ---------------------------------------------------------------------------
// K3: stage0 BN apply + ReLU + stride-2 subsample -> h1 position-major
// grid (375, 4, 2), block 256 (64 ch x 4 positions)
// ---------------------------------------------------------------------------
__global__ void k3_h1()
{
    int c = threadIdx.x & 63;
    int sub = threadIdx.x >> 6;
    int w = blockIdx.x * 4 + sub;
    int h = blockIdx.y, b = blockIdx.z;
    float v = d_out0[((b*64 + c)*8 + 2*h)*3000 + 2*w];
    float y = fmaxf(fmaf(v, d_scale0[c], d_shift0[c]), 0.f);
    d_h1[(((b*4 + h)*1500) + w)*64 + c] = y;
}

// ---------------------------------------------------------------------------
// K4: stage1 fused qkv GEMM  [18048 x 64] @ [64 x 768]
// grid (564, 6), block 256. TM=32, TN=128, K=64.
// ---------------------------------------------------------------------------
__global__ void k4_gemm1()
{
    __shared__ float As[32][64];
    __shared__ float Bs[64][128];
    int tid = threadIdx.x;
    int rowBase = blockIdx.x * 32;
    int colBase = blockIdx.y * 128;

    // Load A tile (zero rows for padding)
    {
        int r = tid >> 3;
        int c = (tid & 7) * 8;
        int prow = rowBase + r;
        int b = prow / 9024; int rem = prow % 9024;
        int hp = rem / 1504; int wp = rem % 1504;
        bool valid = (hp >= 1 && hp < 5 && wp >= 2 && wp < 1502);
        if (valid) {
            const float* src = d_h1 + (((b*4 + (hp-1))*1500) + (wp-2))*64 + c;
            *(float4*)&As[r][c]   = *(const float4*)(src);
            *(float4*)&As[r][c+4] = *(const float4*)(src+4);
        } else {
            float4 z = make_float4(0.f,0.f,0.f,0.f);
            *(float4*)&As[r][c] = z;
            *(float4*)&As[r][c+4] = z;
        }
    }
    // Load B tile
    for (int i = tid; i < 64*32; i += 256) {
        int r = i >> 5; int c4 = i & 31;
        *(float4*)&Bs[r][c4*4] = *(const float4*)&d_Wcat1[r*768 + colBase + c4*4];
    }
    __syncthreads();

    int ty = tid >> 5, tx = tid & 31;
    float acc[4][4] = {};
    #pragma unroll 8
    for (int kk = 0; kk < 64; kk++) {
        float a0 = As[ty*4+0][kk], a1 = As[ty*4+1][kk];
        float a2 = As[ty*4+2][kk], a3 = As[ty*4+3][kk];
        float4 bv = *(float4*)&Bs[kk][tx*4];
        acc[0][0] += a0*bv.x; acc[0][1] += a0*bv.y; acc[0][2] += a0*bv.z; acc[0][3] += a0*bv.w;
        acc[1][0] += a1*bv.x; acc[1][1] += a1*bv.y; acc[1][2] += a1*bv.z; acc[1][3] += a1*bv.w;
        acc[2][0] += a2*bv.x; acc[2][1] += a2*bv.y; acc[2][2] += a2*bv.z; acc[2][3] += a2*bv.w;
        acc[3][0] += a3*bv.x; acc[3][1] += a3*bv.y; acc[3][2] += a3*bv.z; acc[3][3] += a3*bv.w;
    }
    #pragma unroll
    for (int i = 0; i < 4; i++) {
        int prow = rowBase + ty*4 + i;
        float4 o4 = make_float4(acc[i][0], acc[i][1], acc[i][2], acc[i][3]);
        *(float4*)&d_qkv1[(size_t)prow*768 + colBase + tx*4] = o4;
    }
}

// ---------------------------------------------------------------------------
// K5: stage1 attention combine. grid (1500, 4, 2), block 128
// ---------------------------------------------------------------------------
__global__ void k5_attn1()
{
    int w = blockIdx.x, h = blockIdx.y, b = blockIdx.z;
    int tid = threadIdx.x, lane = tid & 31, wrp = tid >> 5;
    __shared__ float sc[10];
    __shared__ float cm[40];

    const float* base = d_qkv1 + (size_t)b * 6 * 1504 * 768;
    const float* qp = base + ((h+1)*1504 + (w+2)) * 768;

    for (int kl = wrp; kl < 10; kl += 4) {
        int i = kl / 5, j = kl % 5;
        const float* kp = base + ((h+i)*1504 + (w+j)) * 768 + 128;
        float p = 0.f;
        #pragma unroll
        for (int u = 0; u < 4; u++) { int o = lane + u*32; p += qp[o] * kp[o]; }
        for (int off = 16; off; off >>= 1) p += __shfl_down_sync(0xffffffffu, p, off);
        if (lane == 0) sc[kl] = p;
    }
    __syncthreads();
    if (tid == 0) {
        float mx = -1e30f;
        for (int kl = 0; kl < 10; kl++) mx = fmaxf(mx, sc[kl]);
        float e[10], s = 0.f;
        for (int kl = 0; kl < 10; kl++) { e[kl] = __expf(sc[kl]-mx); s += e[kl]; }
        float inv = 1.f / s;
        for (int kl = 0; kl < 10; kl++) {
            float a = e[kl] * inv;
            for (int m = 0; m < 4; m++) cm[m*10+kl] = a * d_emb1[m*10+kl];
        }
    }
    __syncthreads();
    float acc = 0.f;
    int o = tid;
    #pragma unroll
    for (int kl = 0; kl < 10; kl++) {
        int i = kl / 5, j = kl % 5;
        const float* vp = base + ((h+i)*1504 + (w+j)) * 768 + 256 + o;
        acc += cm[kl]      * vp[0]
             + cm[10+kl]   * vp[128]
             + cm[20+kl]   * vp[256]
             + cm[30+kl]   * vp[384];
    }
    d_out1[(((b*4 + h)*1500) + w)*128 + o] = acc;
}

// ---------------------------------------------------------------------------
// K6: stage1 BN partial sums (atomic), K6b: finalize
// ---------------------------------------------------------------------------
__global__ void k6_bn1_partial()
{
    int c = threadIdx.x;
    float s = 0.f, s2 = 0.f;
    for (int pos = blockIdx.x; pos < 12000; pos += gridDim.x) {
        float v = d_out1[pos*128 + c];
        s += v; s2 += v*v;
    }
    atomicAdd(&d_sum1[c], s);
    atomicAdd(&d_sumsq1[c], s2);
}

__global__ void k6b_bn1_final(const float* g, const float* bb)
{
    int c = threadIdx.x;
    float n = 12000.f;
    float mean = d_sum1[c] / n;
    float var  = d_sumsq1[c] / n - mean*mean;
    float sc = g[c] * rsqrtf(var + 1e-5f);
    d_scale1[c] = sc;
    d_shift1[c] = bb[c] - mean * sc;
}

// ---------------------------------------------------------------------------
// K7: stage1 BN apply + ReLU + stride-2 subsample -> h2. grid (750,2,2), 128
// ---------------------------------------------------------------------------
__global__ void k7_h2()
{
    int c = threadIdx.x;
    int w = blockIdx.x, h = blockIdx.y, b = blockIdx.z;
    float v = d_out1[(((b*4 + 2*h)*1500) + 2*w)*128 + c];
    float y = fmaxf(fmaf(v, d_scale1[c], d_shift1[c]), 0.f);
    d_h2[(((b*2 + h)*750) + w)*128 + c] = y;
}

// ---------------------------------------------------------------------------
// K8: stage2 fused qkv GEMM (block per padded position). grid (754,2,2), 96
// ---------------------------------------------------------------------------
__global__ void k8_gemm2()
{
    __shared__ float a[128];
    int wp = blockIdx.x, hp = blockIdx.y, b = blockIdx.z;
    int tid = threadIdx.x;
    bool valid = (wp >= 2 && wp < 752);
    const float* src = d_h2 + (((b*2 + hp)*750) + (wp-2))*128;
    for (int i = tid; i < 128; i += 96) a[i] = valid ? src[i] : 0.f;
    __syncthreads();
    float acc = 0.f;
    #pragma unroll 8
    for (int c = 0; c < 128; c++) acc += a[c] * d_Wcat2[c*96 + tid];
    d_qkv2[(((b*2 + hp)*754) + wp)*96 + tid] = acc;
}

// ---------------------------------------------------------------------------
// K9: stage2 attention combine. grid (750, 2), warp per position
// ---------------------------------------------------------------------------
__global__ void k9_attn2()
{
    int w = blockIdx.x, b = blockIdx.y;
    int lane = threadIdx.x;
    const float* base = d_qkv2 + (size_t)b * 2 * 754 * 96;
    const float* qp = base + (w + 2) * 96;   // hp = 0 (no top pad)

    float scl[10];
    float mx = -1e30f;
    #pragma unroll
    for (int kl = 0; kl < 10; kl++) {
        int i = kl / 5, j = kl % 5;
        const float* kp = base + (i*754 + (w+j))*96 + 16;
        float p = (lane < 16) ? qp[lane] * kp[lane] : 0.f;
        for (int off = 8; off; off >>= 1) p += __shfl_xor_sync(0xffffffffu, p, off);
        p = __shfl_sync(0xffffffffu, p, 0);
        scl[kl] = p;
        mx = fmaxf(mx, p);
    }
    float s = 0.f;
    #pragma unroll
    for (int kl = 0; kl < 10; kl++) { scl[kl] = __expf(scl[kl]-mx); s += scl[kl]; }
    float inv = 1.f / s;
    if (lane < 16) {
        float acc = 0.f;
        #pragma unroll
        for (int kl = 0; kl < 10; kl++) {
            int i = kl / 5, j = kl % 5;
            const float* vp = base + (i*754 + (w+j))*96 + 32 + lane;
            float a = scl[kl] * inv;
            #pragma unroll
            for (int m = 0; m < 4; m++) acc += a * d_emb2[m*10+kl] * vp[m*16];
        }
        d_out2[(b*750 + w)*16 + lane] = acc;
    }
}

// ---------------------------------------------------------------------------
// K10: stage2 BN stats (single block)
// ---------------------------------------------------------------------------
__global__ void k10_bn2(const float* g, const float* bb)
{
    int tid = threadIdx.x;
    int c = tid & 15, chunk = tid >> 4;   // 32 chunks x 16 ch
    float s = 0.f, s2 = 0.f;
    for (int pos = chunk; pos < 1500; pos += 32) {
        float v = d_out2[pos*16 + c];
        s += v; s2 += v*v;
    }
    __shared__ float sh[512], sh2[512];
    sh[tid] = s; sh2[tid] = s2;
    __syncthreads();
    for (int st = 256; st >= 16; st >>= 1) {
        if (tid < st) { sh[tid] += sh[tid+st]; sh2[tid] += sh2[tid+st]; }
        __syncthreads();
    }
    if (tid < 16) {
        float n = 1500.f;
        float mean = sh[tid] / n;
        float var  = sh2[tid] / n - mean*mean;
        float sc = g[tid] * rsqrtf(var + 1e-5f);
        d_scale2[tid] = sc;
        d_shift2[tid] = bb[tid] - mean * sc;
    }
}

// ---------------------------------------------------------------------------
// K11: BN apply + ReLU + AvgPool(1,56) -> out [2,16,1,13]. grid (13,16,2), 64
// ---------------------------------------------------------------------------
__global__ void k11_final(float* out)
{
    int n = blockIdx.x, c = blockIdx.y, b = blockIdx.z;
    int t = threadIdx.x;
    float v = 0.f;
    if (t < 56) {
        float raw = d_out2[(b*750 + n*56 + t)*16 + c];
        v = fmaxf(fmaf(raw, d_scale2[c], d_shift2[c]), 0.f);
    }
    __shared__ float sh[64];
    sh[t] = v;
    __syncthreads();
    for (int st = 32; st; st >>= 1) {
        if (t < st) sh[t] += sh[t+st];
        __syncthreads();
    }
    if (t == 0) out[(b*16 + c)*13 + n] = sh[0] * (1.f/56.f);
}

// ---------------------------------------------------------------------------
extern "C" void kernel_launch(void* const* d_in, const int* in_sizes, int n_in,
                              void* d_out, int out_size)
{
    const float* x     = (const float*)d_in[0];
    const float* p0_q  = (const float*)d_in[1];
    const float* p0_k  = (const float*)d_in[2];
    const float* p0_v  = (const float*)d_in[3];
    const float* p0_ea = (const float*)d_in[4];
    const float* p0_eb = (const float*)d_in[5];
    const float* p0_em = (const float*)d_in[6];
    const float* p0_g  = (const float*)d_in[7];
    const float* p0_b  = (const float*)d_in[8];
    const float* p1_q  = (const float*)d_in[9];
    const float* p1_k  = (const float*)d_in[10];
    const float* p1_v  = (const float*)d_in[11];
    const float* p1_ea = (const float*)d_in[12];
    const float* p1_eb = (const float*)d_in[13];
    const float* p1_em = (const float*)d_in[14];
    const float* p1_g  = (const float*)d_in[15];
    const float* p1_b  = (const float*)d_in[16];
    const float* p2_q  = (const float*)d_in[17];
    const float* p2_k  = (const float*)d_in[18];
    const float* p2_v  = (const float*)d_in[19];
    const float* p2_ea = (const float*)d_in[20];
    const float* p2_eb = (const float*)d_in[21];
    const float* p2_em = (const float*)d_in[22];
    const float* p2_g  = (const float*)d_in[23];
    const float* p2_b  = (const float*)d_in[24];
    float* out = (float*)d_out;

    k0_pre<<<1, 256>>>(p0_q, p0_k, p0_v, p0_ea, p0_eb, p0_em,
                       p1_q, p1_k, p1_v, p1_ea, p1_eb, p1_em,
                       p2_q, p2_k, p2_v, p2_ea, p2_eb, p2_em);
    k1_stem0<<<dim3(24, 8, 2), 128>>>(x);
    k2_bn0<<<64, 256>>>(p0_g, p0_b);
    k3_h1<<<dim3(375, 4, 2), 256>>>();
    k4_gemm1<<<dim3(564, 6), 256>>>();
    k5_attn1<<<dim3(1500, 4, 2), 128>>>();
    k6_bn1_partial<<<48, 128>>>();
    k6b_bn1_final<<<1, 128>>>(p1_g, p1_b);
    k7_h2<<<dim3(750, 2, 2), 128>>>();
    k8_gemm2<<<dim3(754, 2, 2), 96>>>();
    k9_attn2<<<dim3(750, 2), 32>>>();
    k10_bn2<<<1, 512>>>(p2_g, p2_b);
    k11_final<<<dim3(13, 16, 2), 64>>>(out);
}

// round 2
// speedup vs baseline: 1.7950x; 1.7950x over previous
#include <cuda_runtime.h>
#include <cuda_bf16.h>
#include <math.h>
#include <stdint.h>

// ---------------------------------------------------------------------------
// Static device scratch
// ---------------------------------------------------------------------------
__device__ float d_g0[5*12000];                // stage0 g-vectors at subsampled positions [l][b*6000+h'*1500+w']
__device__ float d_h1[2*4*1500*64];            // stage1 input, position-major
__device__ float d_qkv1[2*6*1504*768];         // stage1 q|k|v on padded grid
__device__ float d_o1raw[2*2*750*128];         // stage1 pre-BN output at subsampled positions
__device__ float d_qkv2[2*2*754*96];           // stage2 q|k|v on padded grid
__device__ float d_out2[2*750*16];             // stage2 pre-BN output

__device__ float d_W1hi[64*768];               // stage1 fused weights, tf32 hi part
__device__ float d_W1lo[64*768];               // stage1 fused weights, tf32 lo part
__device__ float d_Wcat2[128*96];              // stage2 fused weights (fp32)
__device__ float d_Weff0[5*64];                // stage0 folded mixture value weights
__device__ float d_emb1[4*10];
__device__ float d_emb2[4*10];
__device__ float d_C0;

__device__ float d_S0[30];                     // stage0 stats: [0..4]=S_l, [5+l*5+l2]=G_{l,l2} (l<=l2)
__device__ float d_sum1[128], d_sumsq1[128];
__device__ float d_sum2[16],  d_sumsq2[16];

__device__ __forceinline__ uint32_t f2tf(float f) {
    uint32_t u;
    asm("cvt.rna.tf32.f32 %0, %1;" : "=r"(u) : "f"(f));
    return u;
}

__device__ __forceinline__ void mma_tf32(float4& c,
    uint32_t a0, uint32_t a1, uint32_t a2, uint32_t a3,
    uint32_t b0, uint32_t b1)
{
    asm volatile(
        "mma.sync.aligned.m16n8k8.row.col.f32.tf32.tf32.f32 "
        "{%0,%1,%2,%3},{%4,%5,%6,%7},{%8,%9},{%0,%1,%2,%3};"
        : "+f"(c.x), "+f"(c.y), "+f"(c.z), "+f"(c.w)
        : "r"(a0), "r"(a1), "r"(a2), "r"(a3), "r"(b0), "r"(b1));
}

// ---------------------------------------------------------------------------
// K0: precompute embeddings, fused weights (tf32 hi/lo for stage1), zero stats
// ---------------------------------------------------------------------------
__global__ void k0_pre(const float* p0_q, const float* p0_k, const float* p0_v,
                       const float* p0_ea, const float* p0_eb, const float* p0_em,
                       const float* p1_q, const float* p1_k, const float* p1_v,
                       const float* p1_ea, const float* p1_eb, const float* p1_em,
                       const float* p2_q, const float* p2_k, const float* p2_v,
                       const float* p2_ea, const float* p2_eb, const float* p2_em)
{
    int t = threadIdx.x;
    __shared__ float logit0[4][5], logit1[4][10], logit2[4][10];
    __shared__ float emb0s[4][5];

    if (t == 0) {
        float s = 0.f;
        for (int o = 0; o < 64; o++) s += p0_q[o] * p0_k[o];
        d_C0 = s;
    }
    if (t >= 128 && t < 148) {
        int u = t - 128; int m = u / 5, j = u % 5;
        float la = 0.f, lb = 0.f;
        for (int o = 0; o < 64; o++) {
            la += p0_em[m*64+o] * p0_ea[o];
            lb += p0_em[m*64+o] * p0_eb[o*5+j];
        }
        logit0[m][j] = la + lb;
    }
    if (t < 40) {
        int m = t / 10, kl = t % 10, i = kl / 5, j = kl % 5;
        float la = 0.f, lb = 0.f;
        for (int o = 0; o < 128; o++) {
            la += p1_em[m*128+o] * p1_ea[o*2+i];
            lb += p1_em[m*128+o] * p1_eb[o*5+j];
        }
        logit1[m][kl] = la + lb;
    }
    if (t >= 64 && t < 104) {
        int u = t - 64; int m = u / 10, kl = u % 10, i = kl / 5, j = kl % 5;
        float la = 0.f, lb = 0.f;
        for (int o = 0; o < 16; o++) {
            la += p2_em[m*16+o] * p2_ea[o*2+i];
            lb += p2_em[m*16+o] * p2_eb[o*5+j];
        }
        logit2[m][kl] = la + lb;
    }
    __syncthreads();
    if (t < 5) {
        float mx = -1e30f;
        for (int m = 0; m < 4; m++) mx = fmaxf(mx, logit0[m][t]);
        float e[4], s = 0.f;
        for (int m = 0; m < 4; m++) { e[m] = __expf(logit0[m][t]-mx); s += e[m]; }
        for (int m = 0; m < 4; m++) emb0s[m][t] = e[m] / s;
    }
    if (t >= 32 && t < 42) {
        int kl = t - 32;
        float mx = -1e30f;
        for (int m = 0; m < 4; m++) mx = fmaxf(mx, logit1[m][kl]);
        float e[4], s = 0.f;
        for (int m = 0; m < 4; m++) { e[m] = __expf(logit1[m][kl]-mx); s += e[m]; }
        for (int m = 0; m < 4; m++) d_emb1[m*10+kl] = e[m] / s;
    }
    if (t >= 64 && t < 74) {
        int kl = t - 64;
        float mx = -1e30f;
        for (int m = 0; m < 4; m++) mx = fmaxf(mx, logit2[m][kl]);
        float e[4], s = 0.f;
        for (int m = 0; m < 4; m++) { e[m] = __expf(logit2[m][kl]-mx); s += e[m]; }
        for (int m = 0; m < 4; m++) d_emb2[m*10+kl] = e[m] / s;
    }
    __syncthreads();
    for (int idx = t; idx < 5*64; idx += blockDim.x) {
        int l = idx / 64, o = idx % 64;
        float s = 0.f;
        for (int m = 0; m < 4; m++) s += emb0s[m][l] * p0_v[m*64+o];
        d_Weff0[idx] = s;
    }
    // stage1 fused weights -> tf32 hi/lo split
    for (int idx = t; idx < 64*768; idx += blockDim.x) {
        int c = idx / 768, j = idx % 768;
        float v;
        if (j < 128)       v = p1_q[c*128 + j];
        else if (j < 256)  v = p1_k[c*128 + (j-128)];
        else { int m = (j-256) >> 7, o = (j-256) & 127; v = p1_v[(m*64+c)*128 + o]; }
        float hi = __uint_as_float(f2tf(v));
        d_W1hi[idx] = hi;
        d_W1lo[idx] = __uint_as_float(f2tf(v - hi));
    }
    for (int idx = t; idx < 128*96; idx += blockDim.x) {
        int c = idx / 96, j = idx % 96;
        float v;
        if (j < 16)       v = p2_q[c*16 + j];
        else if (j < 32)  v = p2_k[c*16 + (j-16)];
        else { int m = (j-32) >> 4, o = (j-32) & 15; v = p2_v[(m*128+c)*16 + o]; }
        d_Wcat2[idx] = v;
    }
    // zero stats accumulators
    if (t < 30) d_S0[t] = 0.f;
    if (t < 128) { d_sum1[t] = 0.f; d_sumsq1[t] = 0.f; }
    if (t < 16)  { d_sum2[t] = 0.f; d_sumsq2[t] = 0.f; }
}

// ---------------------------------------------------------------------------
// K1: stage0 attention -> per-position g[5], block-reduced low-rank BN stats,
//     store g only at subsampled positions. grid (24,8,2), block 128
// ---------------------------------------------------------------------------
__global__ void k1_stem0(const float* x)
{
    int tid = threadIdx.x;
    int w = blockIdx.x * 128 + tid;
    int h = blockIdx.y, b = blockIdx.z;
    bool valid = (w < 3000);

    float g[5] = {0.f,0.f,0.f,0.f,0.f};
    if (valid) {
        const float* xr = x + (b*8 + h) * 3000;
        float xc = xr[w];
        float C0 = d_C0;
        float xl[5], sc[5];
        float mx = -1e30f;
        #pragma unroll
        for (int l = 0; l < 5; l++) {
            int c = w + l - 2;
            xl[l] = (c >= 0 && c < 3000) ? xr[c] : 0.f;
            sc[l] = xc * xl[l] * C0;
            mx = fmaxf(mx, sc[l]);
        }
        float s = 0.f;
        #pragma unroll
        for (int l = 0; l < 5; l++) { sc[l] = __expf(sc[l]-mx); s += sc[l]; }
        float inv = 1.f / s;
        #pragma unroll
        for (int l = 0; l < 5; l++) g[l] = sc[l] * inv * xl[l];
    }

    // 20 stats: 5 sums + 15 upper-tri products
    float st[20];
    {
        int si = 0;
        #pragma unroll
        for (int l = 0; l < 5; l++) st[si++] = g[l];
        #pragma unroll
        for (int l = 0; l < 5; l++)
            #pragma unroll
            for (int l2 = l; l2 < 5; l2++) st[si++] = g[l]*g[l2];
    }
    #pragma unroll
    for (int i = 0; i < 20; i++)
        #pragma unroll
        for (int off = 16; off; off >>= 1)
            st[i] += __shfl_xor_sync(0xffffffffu, st[i], off);

    __shared__ float red[4][20];
    int lane = tid & 31, wrp = tid >> 5;
    if (lane == 0)
        for (int i = 0; i < 20; i++) red[wrp][i] = st[i];
    __syncthreads();
    if (tid < 20) {
        float v = red[0][tid] + red[1][tid] + red[2][tid] + red[3][tid];
        int slot;
        if (tid < 5) slot = tid;
        else {
            int k = tid - 5, l = 0;
            while (k >= 5 - l) { k -= 5 - l; l++; }
            slot = 5 + l*5 + (l + k);
        }
        atomicAdd(&d_S0[slot], v);
    }

    if (valid && !(h & 1) && !(w & 1)) {
        int p = b*6000 + (h>>1)*1500 + (w>>1);
        #pragma unroll
        for (int l = 0; l < 5; l++) d_g0[l*12000 + p] = g[l];
    }
}

// ---------------------------------------------------------------------------
// K3: stage0 BN (scale from low-rank stats, inline) + ReLU, g -> h1
// grid 3000, block 256 (4 positions x 64 channels)
// ---------------------------------------------------------------------------
__global__ void k3_h1(const float* g0, const float* b0)
{
    __shared__ float sW[5*64];
    __shared__ float sScale[64], sShift[64];
    int tid = threadIdx.x;
    for (int i = tid; i < 320; i += 256) sW[i] = d_Weff0[i];
    __syncthreads();
    if (tid < 64) {
        int c = tid;
        float Wc[5];
        #pragma unroll
        for (int l = 0; l < 5; l++) Wc[l] = sW[l*64 + c];
        float mn = 0.f, mq = 0.f;
        #pragma unroll
        for (int l = 0; l < 5; l++) {
            mn += d_S0[l] * Wc[l];
            #pragma unroll
            for (int l2 = 0; l2 < 5; l2++) {
                int lo = l < l2 ? l : l2, hi = l < l2 ? l2 : l;
                mq += d_S0[5 + lo*5 + hi] * Wc[l] * Wc[l2];
            }
        }
        float n = 48000.f;
        float mean = mn / n;
        float var  = mq / n - mean*mean;
        float sc = g0[c] * rsqrtf(var + 1e-5f);
        sScale[c] = sc;
        sShift[c] = b0[c] - mean * sc;
    }
    __syncthreads();

    int c = tid & 63;
    int p = blockIdx.x * 4 + (tid >> 6);
    float a = 0.f;
    #pragma unroll
    for (int l = 0; l < 5; l++) a += d_g0[l*12000 + p] * sW[l*64 + c];
    d_h1[p*64 + c] = fmaxf(fmaf(a, sScale[c], sShift[c]), 0.f);
}

// ---------------------------------------------------------------------------
// K4: stage1 qkv GEMM via tf32 tensor cores, 3-term hi/lo split (~fp32 acc).
// [18048 x 64] @ [64 x 768]. Block tile 64x64, 128 threads. grid (282, 12).
// ---------------------------------------------------------------------------
#define K4_SMEM ((64*68 + 2*64*72) * 4)

__global__ void k4_gemm1()
{
    extern __shared__ float sh[];
    float* As = sh;                 // [64][68]
    float* Bh = sh + 64*68;         // [64][72]
    float* Bl = Bh + 64*72;         // [64][72]

    int tid = threadIdx.x;
    int rowBase = blockIdx.x * 64;
    int colBase = blockIdx.y * 64;

    // Load A tile (zeros for padded rows)
    {
        int r = tid >> 1;
        int half = (tid & 1) * 32;
        int prow = rowBase + r;
        int b = prow / 9024; int rem = prow % 9024;
        int hp = rem / 1504; int wp = rem % 1504;
        bool valid = (hp >= 1 && hp < 5 && wp >= 2 && wp < 1502);
        float* dst = As + r*68 + half;
        if (valid) {
            const float* src = d_h1 + (((b*4 + (hp-1))*1500) + (wp-2))*64 + half;
            #pragma unroll
            for (int u = 0; u < 8; u++)
                *(float4*)(dst + u*4) = *(const float4*)(src + u*4);
        } else {
            float4 z = make_float4(0.f,0.f,0.f,0.f);
            #pragma unroll
            for (int u = 0; u < 8; u++) *(float4*)(dst + u*4) = z;
        }
    }
    // Load B tiles
    for (int i = tid; i < 4096; i += 128) {
        int r = i >> 6, c = i & 63;
        Bh[r*72 + c] = d_W1hi[r*768 + colBase + c];
        Bl[r*72 + c] = d_W1lo[r*768 + colBase + c];
    }
    __syncthreads();

    int lane = tid & 31, wid = tid >> 5;
    int g = lane >> 2, tg = lane & 3;
    int mr = wid * 16;

    float4 acc[8];
    #pragma unroll
    for (int i = 0; i < 8; i++) acc[i] = make_float4(0.f,0.f,0.f,0.f);

    #pragma unroll
    for (int ks = 0; ks < 8; ks++) {
        int k0 = ks * 8;
        float a0f = As[(mr+g  )*68 + k0+tg  ];
        float a1f = As[(mr+g+8)*68 + k0+tg  ];
        float a2f = As[(mr+g  )*68 + k0+tg+4];
        float a3f = As[(mr+g+8)*68 + k0+tg+4];
        uint32_t ah0 = f2tf(a0f), ah1 = f2tf(a1f), ah2 = f2tf(a2f), ah3 = f2tf(a3f);
        uint32_t al0 = f2tf(a0f - __uint_as_float(ah0));
        uint32_t al1 = f2tf(a1f - __uint_as_float(ah1));
        uint32_t al2 = f2tf(a2f - __uint_as_float(ah2));
        uint32_t al3 = f2tf(a3f - __uint_as_float(ah3));

        #pragma unroll
        for (int nt = 0; nt < 8; nt++) {
            int n0 = nt * 8;
            uint32_t bh0 = __float_as_uint(Bh[(k0+tg  )*72 + n0 + g]);
            uint32_t bh1 = __float_as_uint(Bh[(k0+tg+4)*72 + n0 + g]);
            uint32_t bl0 = __float_as_uint(Bl[(k0+tg  )*72 + n0 + g]);
            uint32_t bl1 = __float_as_uint(Bl[(k0+tg+4)*72 + n0 + g]);
            mma_tf32(acc[nt], ah0, ah1, ah2, ah3, bh0, bh1);
            mma_tf32(acc[nt], ah0, ah1, ah2, ah3, bl0, bl1);
            mma_tf32(acc[nt], al0, al1, al2, al3, bh0, bh1);
        }
    }

    int row0 = rowBase + mr + g;
    #pragma unroll
    for (int nt = 0; nt < 8; nt++) {
        int col = colBase + nt*8 + tg*2;
        *(float2*)&d_qkv1[(size_t)row0*768 + col]     = make_float2(acc[nt].x, acc[nt].y);
        *(float2*)&d_qkv1[(size_t)(row0+8)*768 + col] = make_float2(acc[nt].z, acc[nt].w);
    }
}

// ---------------------------------------------------------------------------
// K5: stage1 attention combine, 10 positions/block + fused BN stats,
//     writes only subsampled pre-BN output. grid (150, 4, 2), block 128
// ---------------------------------------------------------------------------
__global__ void k5_attn1()
{
    int w0 = blockIdx.x * 10, h = blockIdx.y, b = blockIdx.z;
    int tid = threadIdx.x, lane = tid & 31, wrp = tid >> 5;
    __shared__ float ssc[10][10];
    __shared__ float cm[10][40];

    const float* base = d_qkv1 + (size_t)b * 6 * 1504 * 768;

    for (int p = wrp; p < 10; p += 4) {
        int w = w0 + p;
        const float* qp = base + ((h+1)*1504 + (w+2)) * 768;
        float q0 = qp[lane], q1 = qp[lane+32], q2 = qp[lane+64], q3 = qp[lane+96];
        #pragma unroll
        for (int kl = 0; kl < 10; kl++) {
            int i = kl / 5, j = kl % 5;
            const float* kp = base + ((h+i)*1504 + (w+j)) * 768 + 128;
            float s = q0*kp[lane] + q1*kp[lane+32] + q2*kp[lane+64] + q3*kp[lane+96];
            #pragma unroll
            for (int off = 16; off; off >>= 1) s += __shfl_xor_sync(0xffffffffu, s, off);
            if (lane == 0) ssc[p][kl] = s;
        }
    }
    __syncthreads();
    if (tid < 10) {
        float mx = -1e30f;
        #pragma unroll
        for (int kl = 0; kl < 10; kl++) mx = fmaxf(mx, ssc[tid][kl]);
        float e[10], s = 0.f;
        #pragma unroll
        for (int kl = 0; kl < 10; kl++) { e[kl] = __expf(ssc[tid][kl]-mx); s += e[kl]; }
        float inv = 1.f / s;
        #pragma unroll
        for (int kl = 0; kl < 10; kl++) {
            float a = e[kl] * inv;
            #pragma unroll
            for (int m = 0; m < 4; m++) cm[tid][m*10+kl] = a * d_emb1[m*10+kl];
        }
    }
    __syncthreads();

    int o = tid;
    float s1 = 0.f, s2 = 0.f;
    for (int p = 0; p < 10; p++) {
        float acc = 0.f;
        #pragma unroll
        for (int kl = 0; kl < 10; kl++) {
            int i = kl / 5, j = kl % 5;
            const float* vp = base + ((h+i)*1504 + (w0+p+j)) * 768 + 256 + o;
            acc += cm[p][kl]    * vp[0]
                 + cm[p][10+kl] * vp[128]
                 + cm[p][20+kl] * vp[256]
                 + cm[p][30+kl] * vp[384];
        }
        s1 += acc; s2 += acc*acc;
        if (!(h & 1) && !((w0+p) & 1))
            d_o1raw[((b*2 + (h>>1))*750 + ((w0+p)>>1))*128 + o] = acc;
    }
    atomicAdd(&d_sum1[o], s1);
    atomicAdd(&d_sumsq1[o], s2);
}

// ---------------------------------------------------------------------------
// K8: stage2 qkv GEMM with inline stage1-BN+ReLU on load. grid (754,2,2), 96
// ---------------------------------------------------------------------------
__global__ void k8_gemm2(const float* g1, const float* b1)
{
    __shared__ float a[128];
    int wp = blockIdx.x, hp = blockIdx.y, b = blockIdx.z;
    int tid = threadIdx.x;
    bool valid = (wp >= 2 && wp < 752);
    for (int i = tid; i < 128; i += 96) {
        float v = 0.f;
        if (valid) {
            float raw = d_o1raw[(((b*2 + hp)*750) + (wp-2))*128 + i];
            float n = 12000.f;
            float mean = d_sum1[i] / n;
            float var  = d_sumsq1[i] / n - mean*mean;
            float sc = g1[i] * rsqrtf(var + 1e-5f);
            v = fmaxf(fmaf(raw, sc, b1[i] - mean*sc), 0.f);
        }
        a[i] = v;
    }
    __syncthreads();
    float acc = 0.f;
    #pragma unroll 8
    for (int c = 0; c < 128; c++) acc += a[c] * d_Wcat2[c*96 + tid];
    d_qkv2[(((b*2 + hp)*754) + wp)*96 + tid] = acc;
}

// ---------------------------------------------------------------------------
// K9: stage2 attention combine, 5 positions/warp + fused BN stats.
// grid (150, 2), block 32
// ---------------------------------------------------------------------------
__global__ void k9_attn2()
{
    int w0 = blockIdx.x * 5, b = blockIdx.y;
    int lane = threadIdx.x;
    const float* base = d_qkv2 + (size_t)b * 2 * 754 * 96;
    float s1 = 0.f, s2 = 0.f;

    for (int p = 0; p < 5; p++) {
        int w = w0 + p;
        const float* qp = base + (w + 2) * 96;
        float scl[10];
        float mx = -1e30f;
        #pragma unroll
        for (int kl = 0; kl < 10; kl++) {
            int i = kl / 5, j = kl % 5;
            const float* kp = base + (i*754 + (w+j))*96 + 16;
            float pr = (lane < 16) ? qp[lane] * kp[lane] : 0.f;
            #pragma unroll
            for (int off = 8; off; off >>= 1) pr += __shfl_xor_sync(0xffffffffu, pr, off);
            pr = __shfl_sync(0xffffffffu, pr, 0);
            scl[kl] = pr;
            mx = fmaxf(mx, pr);
        }
        float s = 0.f;
        #pragma unroll
        for (int kl = 0; kl < 10; kl++) { scl[kl] = __expf(scl[kl]-mx); s += scl[kl]; }
        float inv = 1.f / s;
        if (lane < 16) {
            float acc = 0.f;
            #pragma unroll
            for (int kl = 0; kl < 10; kl++) {
                int i = kl / 5, j = kl % 5;
                const float* vp = base + (i*754 + (w+j))*96 + 32 + lane;
                float aw = scl[kl] * inv;
                #pragma unroll
                for (int m = 0; m < 4; m++) acc += aw * d_emb2[m*10+kl] * vp[m*16];
            }
            d_out2[(b*750 + w)*16 + lane] = acc;
            s1 += acc; s2 += acc*acc;
        }
    }
    if (lane < 16) {
        atomicAdd(&d_sum2[lane], s1);
        atomicAdd(&d_sumsq2[lane], s2);
    }
}

// ---------------------------------------------------------------------------
// K11: stage2 BN (inline) + ReLU + AvgPool(1,56) -> out [2,16,1,13]
// grid (13,16,2), block 64
// ---------------------------------------------------------------------------
__global__ void k11_final(float* out, const float* g2, const float* b2)
{
    int n = blockIdx.x, c = blockIdx.y, b = blockIdx.z;
    int t = threadIdx.x;
    float nn = 1500.f;
    float mean = d_sum2[c] / nn;
    float var  = d_sumsq2[c] / nn - mean*mean;
    float sc = g2[c] * rsqrtf(var + 1e-5f);
    float sf = b2[c] - mean * sc;

    float v = 0.f;
    if (t < 56) {
        float raw = d_out2[(b*750 + n*56 + t)*16 + c];
        v = fmaxf(fmaf(raw, sc, sf), 0.f);
    }
    __shared__ float shm[64];
    shm[t] = v;
    __syncthreads();
    for (int st = 32; st; st >>= 1) {
        if (t < st) shm[t] += shm[t+st];
        __syncthreads();
    }
    if (t == 0) out[(b*16 + c)*13 + n] = shm[0] * (1.f/56.f);
}

// ---------------------------------------------------------------------------
extern "C" void kernel_launch(void* const* d_in, const int* in_sizes, int n_in,
                              void* d_out, int out_size)
{
    const float* x     = (const float*)d_in[0];
    const float* p0_q  = (const float*)d_in[1];
    const float* p0_k  = (const float*)d_in[2];
    const float* p0_v  = (const float*)d_in[3];
    const float* p0_ea = (const float*)d_in[4];
    const float* p0_eb = (const float*)d_in[5];
    const float* p0_em = (const float*)d_in[6];
    const float* p0_g  = (const float*)d_in[7];
    const float* p0_b  = (const float*)d_in[8];
    const float* p1_q  = (const float*)d_in[9];
    const float* p1_k  = (const float*)d_in[10];
    const float* p1_v  = (const float*)d_in[11];
    const float* p1_ea = (const float*)d_in[12];
    const float* p1_eb = (const float*)d_in[13];
    const float* p1_em = (const float*)d_in[14];
    const float* p1_g  = (const float*)d_in[15];
    const float* p1_b  = (const float*)d_in[16];
    const float* p2_q  = (const float*)d_in[17];
    const float* p2_k  = (const float*)d_in[18];
    const float* p2_v  = (const float*)d_in[19];
    const float* p2_ea = (const float*)d_in[20];
    const float* p2_eb = (const float*)d_in[21];
    const float* p2_em = (const float*)d_in[22];
    const float* p2_g  = (const float*)d_in[23];
    const float* p2_b  = (const float*)d_in[24];
    float* out = (float*)d_out;

    static int smem_set = 0;
    if (!smem_set) {
        cudaFuncSetAttribute(k4_gemm1, cudaFuncAttributeMaxDynamicSharedMemorySize, K4_SMEM);
        smem_set = 1;
    }

    k0_pre<<<1, 256>>>(p0_q, p0_k, p0_v, p0_ea, p0_eb, p0_em,
                       p1_q, p1_k, p1_v, p1_ea, p1_eb, p1_em,
                       p2_q, p2_k, p2_v, p2_ea, p2_eb, p2_em);
    k1_stem0<<<dim3(24, 8, 2), 128>>>(x);
    k3_h1<<<3000, 256>>>(p0_g, p0_b);
    k4_gemm1<<<dim3(282, 12), 128, K4_SMEM>>>();
    k5_attn1<<<dim3(150, 4, 2), 128>>>();
    k8_gemm2<<<dim3(754, 2, 2), 96>>>(p1_g, p1_b);
    k9_attn2<<<dim3(150, 2), 32>>>();
    k11_final<<<dim3(13, 16, 2), 64>>>(out, p2_g, p2_b);
}

// round 3
// speedup vs baseline: 2.2470x; 1.2518x over previous
#include <cuda_runtime.h>
#include <cuda_bf16.h>
#include <math.h>
#include <stdint.h>

// ---------------------------------------------------------------------------
// Static device scratch
// ---------------------------------------------------------------------------
__device__ float d_g0[5*12000];                 // stage0 g-vectors at subsampled positions
__device__ __nv_bfloat16 d_h1h[12000*64];       // stage1 input bf16 hi plane
__device__ __nv_bfloat16 d_h1l[12000*64];       // stage1 input bf16 lo plane
__device__ float d_qkv1[2*6*1504*768];          // stage1 q|k|v on padded grid (fp32)
__device__ float d_o1raw[2*2*750*128];          // stage1 pre-BN output at subsampled positions
__device__ float d_qkv2[2*2*754*96];            // stage2 q|k|v on padded grid
__device__ float d_out2[2*750*16];              // stage2 pre-BN output

__device__ __nv_bfloat16 d_W1bh[768*64];        // stage1 fused weights, [n][k] bf16 hi
__device__ __nv_bfloat16 d_W1bl[768*64];        // stage1 fused weights, [n][k] bf16 lo
__device__ float d_Wcat2[128*96];
__device__ float d_Weff0[5*64];
__device__ float d_emb1[4*10];
__device__ float d_emb2[4*10];
__device__ float d_C0;

__device__ float d_S0[30];
__device__ float d_sum1[128], d_sumsq1[128];
__device__ float d_sum2[16],  d_sumsq2[16];

__device__ __forceinline__ void mma_bf16(float4& c,
    uint32_t a0, uint32_t a1, uint32_t a2, uint32_t a3,
    uint32_t b0, uint32_t b1)
{
    asm volatile(
        "mma.sync.aligned.m16n8k16.row.col.f32.bf16.bf16.f32 "
        "{%0,%1,%2,%3},{%4,%5,%6,%7},{%8,%9},{%0,%1,%2,%3};"
        : "+f"(c.x), "+f"(c.y), "+f"(c.z), "+f"(c.w)
        : "r"(a0), "r"(a1), "r"(a2), "r"(a3), "r"(b0), "r"(b1));
}

// ---------------------------------------------------------------------------
// K0: precompute embeddings, fused weights (bf16 hi/lo, [n][k]), zero stats
// ---------------------------------------------------------------------------
__global__ void k0_pre(const float* p0_q, const float* p0_k, const float* p0_v,
                       const float* p0_ea, const float* p0_eb, const float* p0_em,
                       const float* p1_q, const float* p1_k, const float* p1_v,
                       const float* p1_ea, const float* p1_eb, const float* p1_em,
                       const float* p2_q, const float* p2_k, const float* p2_v,
                       const float* p2_ea, const float* p2_eb, const float* p2_em)
{
    int t = threadIdx.x;
    __shared__ float logit0[4][5], logit1[4][10], logit2[4][10];
    __shared__ float emb0s[4][5];

    if (t == 0) {
        float s = 0.f;
        for (int o = 0; o < 64; o++) s += p0_q[o] * p0_k[o];
        d_C0 = s;
    }
    if (t >= 128 && t < 148) {
        int u = t - 128; int m = u / 5, j = u % 5;
        float la = 0.f, lb = 0.f;
        for (int o = 0; o < 64; o++) {
            la += p0_em[m*64+o] * p0_ea[o];
            lb += p0_em[m*64+o] * p0_eb[o*5+j];
        }
        logit0[m][j] = la + lb;
    }
    if (t < 40) {
        int m = t / 10, kl = t % 10, i = kl / 5, j = kl % 5;
        float la = 0.f, lb = 0.f;
        for (int o = 0; o < 128; o++) {
            la += p1_em[m*128+o] * p1_ea[o*2+i];
            lb += p1_em[m*128+o] * p1_eb[o*5+j];
        }
        logit1[m][kl] = la + lb;
    }
    if (t >= 64 && t < 104) {
        int u = t - 64; int m = u / 10, kl = u % 10, i = kl / 5, j = kl % 5;
        float la = 0.f, lb = 0.f;
        for (int o = 0; o < 16; o++) {
            la += p2_em[m*16+o] * p2_ea[o*2+i];
            lb += p2_em[m*16+o] * p2_eb[o*5+j];
        }
        logit2[m][kl] = la + lb;
    }
    __syncthreads();
    if (t < 5) {
        float mx = -1e30f;
        for (int m = 0; m < 4; m++) mx = fmaxf(mx, logit0[m][t]);
        float e[4], s = 0.f;
        for (int m = 0; m < 4; m++) { e[m] = __expf(logit0[m][t]-mx); s += e[m]; }
        for (int m = 0; m < 4; m++) emb0s[m][t] = e[m] / s;
    }
    if (t >= 32 && t < 42) {
        int kl = t - 32;
        float mx = -1e30f;
        for (int m = 0; m < 4; m++) mx = fmaxf(mx, logit1[m][kl]);
        float e[4], s = 0.f;
        for (int m = 0; m < 4; m++) { e[m] = __expf(logit1[m][kl]-mx); s += e[m]; }
        for (int m = 0; m < 4; m++) d_emb1[m*10+kl] = e[m] / s;
    }
    if (t >= 64 && t < 74) {
        int kl = t - 64;
        float mx = -1e30f;
        for (int m = 0; m < 4; m++) mx = fmaxf(mx, logit2[m][kl]);
        float e[4], s = 0.f;
        for (int m = 0; m < 4; m++) { e[m] = __expf(logit2[m][kl]-mx); s += e[m]; }
        for (int m = 0; m < 4; m++) d_emb2[m*10+kl] = e[m] / s;
    }
    __syncthreads();
    for (int idx = t; idx < 5*64; idx += blockDim.x) {
        int l = idx / 64, o = idx % 64;
        float s = 0.f;
        for (int m = 0; m < 4; m++) s += emb0s[m][l] * p0_v[m*64+o];
        d_Weff0[idx] = s;
    }
    // stage1 fused weights -> bf16 hi/lo, stored [n=768][k=64]
    for (int idx = t; idx < 64*768; idx += blockDim.x) {
        int j = idx / 64, c = idx % 64;   // j = output col (n), c = input ch (k)
        float v;
        if (j < 128)       v = p1_q[c*128 + j];
        else if (j < 256)  v = p1_k[c*128 + (j-128)];
        else { int m = (j-256) >> 7, o = (j-256) & 127; v = p1_v[(m*64+c)*128 + o]; }
        __nv_bfloat16 hi = __float2bfloat16_rn(v);
        d_W1bh[idx] = hi;
        d_W1bl[idx] = __float2bfloat16_rn(v - __bfloat162float(hi));
    }
    for (int idx = t; idx < 128*96; idx += blockDim.x) {
        int c = idx / 96, j = idx % 96;
        float v;
        if (j < 16)       v = p2_q[c*16 + j];
        else if (j < 32)  v = p2_k[c*16 + (j-16)];
        else { int m = (j-32) >> 4, o = (j-32) & 15; v = p2_v[(m*128+c)*16 + o]; }
        d_Wcat2[idx] = v;
    }
    if (t < 30) d_S0[t] = 0.f;
    if (t < 128) { d_sum1[t] = 0.f; d_sumsq1[t] = 0.f; }
    if (t < 16)  { d_sum2[t] = 0.f; d_sumsq2[t] = 0.f; }
}

// ---------------------------------------------------------------------------
// K1: stage0 attention -> g[5] + low-rank BN stats. grid (24,8,2), block 128
// ---------------------------------------------------------------------------
__global__ void k1_stem0(const float* x)
{
    int tid = threadIdx.x;
    int w = blockIdx.x * 128 + tid;
    int h = blockIdx.y, b = blockIdx.z;
    bool valid = (w < 3000);

    float g[5] = {0.f,0.f,0.f,0.f,0.f};
    if (valid) {
        const float* xr = x + (b*8 + h) * 3000;
        float xc = xr[w];
        float C0 = d_C0;
        float xl[5], sc[5];
        float mx = -1e30f;
        #pragma unroll
        for (int l = 0; l < 5; l++) {
            int c = w + l - 2;
            xl[l] = (c >= 0 && c < 3000) ? xr[c] : 0.f;
            sc[l] = xc * xl[l] * C0;
            mx = fmaxf(mx, sc[l]);
        }
        float s = 0.f;
        #pragma unroll
        for (int l = 0; l < 5; l++) { sc[l] = __expf(sc[l]-mx); s += sc[l]; }
        float inv = 1.f / s;
        #pragma unroll
        for (int l = 0; l < 5; l++) g[l] = sc[l] * inv * xl[l];
    }

    float st[20];
    {
        int si = 0;
        #pragma unroll
        for (int l = 0; l < 5; l++) st[si++] = g[l];
        #pragma unroll
        for (int l = 0; l < 5; l++)
            #pragma unroll
            for (int l2 = l; l2 < 5; l2++) st[si++] = g[l]*g[l2];
    }
    #pragma unroll
    for (int i = 0; i < 20; i++)
        #pragma unroll
        for (int off = 16; off; off >>= 1)
            st[i] += __shfl_xor_sync(0xffffffffu, st[i], off);

    __shared__ float red[4][20];
    int lane = tid & 31, wrp = tid >> 5;
    if (lane == 0)
        for (int i = 0; i < 20; i++) red[wrp][i] = st[i];
    __syncthreads();
    if (tid < 20) {
        float v = red[0][tid] + red[1][tid] + red[2][tid] + red[3][tid];
        int slot;
        if (tid < 5) slot = tid;
        else {
            int k = tid - 5, l = 0;
            while (k >= 5 - l) { k -= 5 - l; l++; }
            slot = 5 + l*5 + (l + k);
        }
        atomicAdd(&d_S0[slot], v);
    }

    if (valid && !(h & 1) && !(w & 1)) {
        int p = b*6000 + (h>>1)*1500 + (w>>1);
        #pragma unroll
        for (int l = 0; l < 5; l++) d_g0[l*12000 + p] = g[l];
    }
}

// ---------------------------------------------------------------------------
// K3: stage0 BN (low-rank stats) + ReLU -> h1 bf16 hi/lo. grid 3000, block 256
// ---------------------------------------------------------------------------
__global__ void k3_h1(const float* g0, const float* b0)
{
    __shared__ float sW[5*64];
    __shared__ float sScale[64], sShift[64];
    int tid = threadIdx.x;
    for (int i = tid; i < 320; i += 256) sW[i] = d_Weff0[i];
    __syncthreads();
    if (tid < 64) {
        int c = tid;
        float Wc[5];
        #pragma unroll
        for (int l = 0; l < 5; l++) Wc[l] = sW[l*64 + c];
        float mn = 0.f, mq = 0.f;
        #pragma unroll
        for (int l = 0; l < 5; l++) {
            mn += d_S0[l] * Wc[l];
            #pragma unroll
            for (int l2 = 0; l2 < 5; l2++) {
                int lo = l < l2 ? l : l2, hi = l < l2 ? l2 : l;
                mq += d_S0[5 + lo*5 + hi] * Wc[l] * Wc[l2];
            }
        }
        float n = 48000.f;
        float mean = mn / n;
        float var  = mq / n - mean*mean;
        float sc = g0[c] * rsqrtf(var + 1e-5f);
        sScale[c] = sc;
        sShift[c] = b0[c] - mean * sc;
    }
    __syncthreads();

    int c = tid & 63;
    int p = blockIdx.x * 4 + (tid >> 6);
    float a = 0.f;
    #pragma unroll
    for (int l = 0; l < 5; l++) a += d_g0[l*12000 + p] * sW[l*64 + c];
    float y = fmaxf(fmaf(a, sScale[c], sShift[c]), 0.f);
    __nv_bfloat16 hi = __float2bfloat16_rn(y);
    d_h1h[p*64 + c] = hi;
    d_h1l[p*64 + c] = __float2bfloat16_rn(y - __bfloat162float(hi));
}

// ---------------------------------------------------------------------------
// K4: stage1 qkv GEMM, bf16 3-term hi/lo split, m16n8k16 tensor cores.
// [18048 x 64] @ [64 x 768]. BM=128, BN=64, 256 threads. grid (141, 12).
// ---------------------------------------------------------------------------
#define K4_SMEM ((128*72 + 128*72 + 64*72 + 64*72) * 2)

__global__ void k4_gemm1()
{
    extern __shared__ __nv_bfloat16 sh[];
    __nv_bfloat16* Ah = sh;               // [128][72]
    __nv_bfloat16* Al = Ah + 128*72;      // [128][72]
    __nv_bfloat16* Bh = Al + 128*72;      // [64 n][72 k]
    __nv_bfloat16* Bl = Bh + 64*72;       // [64 n][72 k]

    int tid = threadIdx.x;
    int rowBase = blockIdx.x * 128;
    int colBase = blockIdx.y * 64;

    // Load A tile: 128 rows x 64 k, hi+lo planes (zeros for padded rows)
    {
        int r = tid >> 1;
        int half = (tid & 1) * 32;
        int prow = rowBase + r;
        int b = prow / 9024; int rem = prow % 9024;
        int hp = rem / 1504; int wp = rem % 1504;
        bool valid = (hp >= 1 && hp < 5 && wp >= 2 && wp < 1502);
        __nv_bfloat16* dh = Ah + r*72 + half;
        __nv_bfloat16* dl = Al + r*72 + half;
        if (valid) {
            int pos = ((b*4 + (hp-1))*1500 + (wp-2))*64 + half;
            const uint4* sH = (const uint4*)(d_h1h + pos);
            const uint4* sL = (const uint4*)(d_h1l + pos);
            #pragma unroll
            for (int u = 0; u < 4; u++) {
                ((uint4*)dh)[u] = sH[u];
                ((uint4*)dl)[u] = sL[u];
            }
        } else {
            uint4 z = make_uint4(0,0,0,0);
            #pragma unroll
            for (int u = 0; u < 4; u++) { ((uint4*)dh)[u] = z; ((uint4*)dl)[u] = z; }
        }
    }
    // Load B tile: 64 n x 64 k, hi+lo
    {
        int n = tid >> 2;
        int seg = (tid & 3) * 16;
        const uint4* sH = (const uint4*)(d_W1bh + (colBase + n)*64 + seg);
        const uint4* sL = (const uint4*)(d_W1bl + (colBase + n)*64 + seg);
        uint4* dh = (uint4*)(Bh + n*72 + seg);
        uint4* dl = (uint4*)(Bl + n*72 + seg);
        dh[0] = sH[0]; dh[1] = sH[1];
        dl[0] = sL[0]; dl[1] = sL[1];
    }
    __syncthreads();

    int lane = tid & 31, wid = tid >> 5;
    int g = lane >> 2, tg = lane & 3;
    int mr = wid * 16;

    float4 acc[8];
    #pragma unroll
    for (int i = 0; i < 8; i++) acc[i] = make_float4(0.f,0.f,0.f,0.f);

    #pragma unroll
    for (int ks = 0; ks < 4; ks++) {
        int k0 = ks * 16;
        uint32_t ah0 = *(uint32_t*)&Ah[(mr+g  )*72 + k0 + tg*2];
        uint32_t ah1 = *(uint32_t*)&Ah[(mr+g+8)*72 + k0 + tg*2];
        uint32_t ah2 = *(uint32_t*)&Ah[(mr+g  )*72 + k0 + 8 + tg*2];
        uint32_t ah3 = *(uint32_t*)&Ah[(mr+g+8)*72 + k0 + 8 + tg*2];
        uint32_t al0 = *(uint32_t*)&Al[(mr+g  )*72 + k0 + tg*2];
        uint32_t al1 = *(uint32_t*)&Al[(mr+g+8)*72 + k0 + tg*2];
        uint32_t al2 = *(uint32_t*)&Al[(mr+g  )*72 + k0 + 8 + tg*2];
        uint32_t al3 = *(uint32_t*)&Al[(mr+g+8)*72 + k0 + 8 + tg*2];

        #pragma unroll
        for (int nt = 0; nt < 8; nt++) {
            int n0 = nt * 8;
            uint32_t bh0 = *(uint32_t*)&Bh[(n0+g)*72 + k0 + tg*2];
            uint32_t bh1 = *(uint32_t*)&Bh[(n0+g)*72 + k0 + 8 + tg*2];
            uint32_t bl0 = *(uint32_t*)&Bl[(n0+g)*72 + k0 + tg*2];
            uint32_t bl1 = *(uint32_t*)&Bl[(n0+g)*72 + k0 + 8 + tg*2];
            mma_bf16(acc[nt], ah0, ah1, ah2, ah3, bh0, bh1);
            mma_bf16(acc[nt], ah0, ah1, ah2, ah3, bl0, bl1);
            mma_bf16(acc[nt], al0, al1, al2, al3, bh0, bh1);
        }
    }

    int row0 = rowBase + mr + g;
    #pragma unroll
    for (int nt = 0; nt < 8; nt++) {
        int col = colBase + nt*8 + tg*2;
        *(float2*)&d_qkv1[(size_t)row0*768 + col]     = make_float2(acc[nt].x, acc[nt].y);
        *(float2*)&d_qkv1[(size_t)(row0+8)*768 + col] = make_float2(acc[nt].z, acc[nt].w);
    }
}

// ---------------------------------------------------------------------------
// K5: stage1 attention combine, 10 positions/block + fused BN stats.
// grid (150, 4, 2), block 128
// ---------------------------------------------------------------------------
__global__ void k5_attn1()
{
    int w0 = blockIdx.x * 10, h = blockIdx.y, b = blockIdx.z;
    int tid = threadIdx.x, lane = tid & 31, wrp = tid >> 5;
    __shared__ float ssc[10][10];
    __shared__ float cm[10][40];

    const float* base = d_qkv1 + (size_t)b * 6 * 1504 * 768;

    for (int p = wrp; p < 10; p += 4) {
        int w = w0 + p;
        const float* qp = base + ((h+1)*1504 + (w+2)) * 768;
        float q0 = qp[lane], q1 = qp[lane+32], q2 = qp[lane+64], q3 = qp[lane+96];
        #pragma unroll
        for (int kl = 0; kl < 10; kl++) {
            int i = kl / 5, j = kl % 5;
            const float* kp = base + ((h+i)*1504 + (w+j)) * 768 + 128;
            float s = q0*kp[lane] + q1*kp[lane+32] + q2*kp[lane+64] + q3*kp[lane+96];
            #pragma unroll
            for (int off = 16; off; off >>= 1) s += __shfl_xor_sync(0xffffffffu, s, off);
            if (lane == 0) ssc[p][kl] = s;
        }
    }
    __syncthreads();
    if (tid < 10) {
        float mx = -1e30f;
        #pragma unroll
        for (int kl = 0; kl < 10; kl++) mx = fmaxf(mx, ssc[tid][kl]);
        float e[10], s = 0.f;
        #pragma unroll
        for (int kl = 0; kl < 10; kl++) { e[kl] = __expf(ssc[tid][kl]-mx); s += e[kl]; }
        float inv = 1.f / s;
        #pragma unroll
        for (int kl = 0; kl < 10; kl++) {
            float a = e[kl] * inv;
            #pragma unroll
            for (int m = 0; m < 4; m++) cm[tid][m*10+kl] = a * d_emb1[m*10+kl];
        }
    }
    __syncthreads();

    int o = tid;
    float s1 = 0.f, s2 = 0.f;
    for (int p = 0; p < 10; p++) {
        float acc = 0.f;
        #pragma unroll
        for (int kl = 0; kl < 10; kl++) {
            int i = kl / 5, j = kl % 5;
            const float* vp = base + ((h+i)*1504 + (w0+p+j)) * 768 + 256 + o;
            acc += cm[p][kl]    * vp[0]
                 + cm[p][10+kl] * vp[128]
                 + cm[p][20+kl] * vp[256]
                 + cm[p][30+kl] * vp[384];
        }
        s1 += acc; s2 += acc*acc;
        if (!(h & 1) && !((w0+p) & 1))
            d_o1raw[((b*2 + (h>>1))*750 + ((w0+p)>>1))*128 + o] = acc;
    }
    atomicAdd(&d_sum1[o], s1);
    atomicAdd(&d_sumsq1[o], s2);
}

// ---------------------------------------------------------------------------
// K8: stage2 qkv GEMM w/ inline stage1-BN+ReLU. 2 positions/block.
// grid (377,2,2), block 192
// ---------------------------------------------------------------------------
__global__ void k8_gemm2(const float* g1, const float* b1)
{
    __shared__ float a[2][128];
    int sub = threadIdx.x / 96;          // 0 or 1
    int tid = threadIdx.x % 96;
    int wp = blockIdx.x * 2 + sub;
    int hp = blockIdx.y, b = blockIdx.z;
    bool valid = (wp >= 2 && wp < 752);
    for (int i = tid; i < 128; i += 96) {
        float v = 0.f;
        if (valid) {
            float raw = d_o1raw[(((b*2 + hp)*750) + (wp-2))*128 + i];
            float n = 12000.f;
            float mean = d_sum1[i] / n;
            float var  = d_sumsq1[i] / n - mean*mean;
            float sc = g1[i] * rsqrtf(var + 1e-5f);
            v = fmaxf(fmaf(raw, sc, b1[i] - mean*sc), 0.f);
        }
        a[sub][i] = v;
    }
    __syncthreads();
    float acc = 0.f;
    #pragma unroll 8
    for (int c = 0; c < 128; c++) acc += a[sub][c] * d_Wcat2[c*96 + tid];
    d_qkv2[(((b*2 + hp)*754) + wp)*96 + tid] = acc;
}

// ---------------------------------------------------------------------------
// K9: stage2 attention combine, 5 positions/warp + fused BN stats.
// grid (150, 2), block 32
// ---------------------------------------------------------------------------
__global__ void k9_attn2()
{
    int w0 = blockIdx.x * 5, b = blockIdx.y;
    int lane = threadIdx.x;
    const float* base = d_qkv2 + (size_t)b * 2 * 754 * 96;
    float s1 = 0.f, s2 = 0.f;

    for (int p = 0; p < 5; p++) {
        int w = w0 + p;
        const float* qp = base + (w + 2) * 96;
        float scl[10];
        float mx = -1e30f;
        #pragma unroll
        for (int kl = 0; kl < 10; kl++) {
            int i = kl / 5, j = kl % 5;
            const float* kp = base + (i*754 + (w+j))*96 + 16;
            float pr = (lane < 16) ? qp[lane] * kp[lane] : 0.f;
            #pragma unroll
            for (int off = 8; off; off >>= 1) pr += __shfl_xor_sync(0xffffffffu, pr, off);
            pr = __shfl_sync(0xffffffffu, pr, 0);
            scl[kl] = pr;
            mx = fmaxf(mx, pr);
        }
        float s = 0.f;
        #pragma unroll
        for (int kl = 0; kl < 10; kl++) { scl[kl] = __expf(scl[kl]-mx); s += scl[kl]; }
        float inv = 1.f / s;
        if (lane < 16) {
            float acc = 0.f;
            #pragma unroll
            for (int kl = 0; kl < 10; kl++) {
                int i = kl / 5, j = kl % 5;
                const float* vp = base + (i*754 + (w+j))*96 + 32 + lane;
                float aw = scl[kl] * inv;
                #pragma unroll
                for (int m = 0; m < 4; m++) acc += aw * d_emb2[m*10+kl] * vp[m*16];
            }
            d_out2[(b*750 + w)*16 + lane] = acc;
            s1 += acc; s2 += acc*acc;
        }
    }
    if (lane < 16) {
        atomicAdd(&d_sum2[lane], s1);
        atomicAdd(&d_sumsq2[lane], s2);
    }
}

// ---------------------------------------------------------------------------
// K11: stage2 BN + ReLU + AvgPool(1,56) -> out. grid (13,16,2), block 64
// ---------------------------------------------------------------------------
__global__ void k11_final(float* out, const float* g2, const float* b2)
{
    int n = blockIdx.x, c = blockIdx.y, b = blockIdx.z;
    int t = threadIdx.x;
    float nn = 1500.f;
    float mean = d_sum2[c] / nn;
    float var  = d_sumsq2[c] / nn - mean*mean;
    float sc = g2[c] * rsqrtf(var + 1e-5f);
    float sf = b2[c] - mean * sc;

    float v = 0.f;
    if (t < 56) {
        float raw = d_out2[(b*750 + n*56 + t)*16 + c];
        v = fmaxf(fmaf(raw, sc, sf), 0.f);
    }
    __shared__ float shm[64];
    shm[t] = v;
    __syncthreads();
    for (int st = 32; st; st >>= 1) {
        if (t < st) shm[t] += shm[t+st];
        __syncthreads();
    }
    if (t == 0) out[(b*16 + c)*13 + n] = shm[0] * (1.f/56.f);
}

// ---------------------------------------------------------------------------
extern "C" void kernel_launch(void* const* d_in, const int* in_sizes, int n_in,
                              void* d_out, int out_size)
{
    const float* x     = (const float*)d_in[0];
    const float* p0_q  = (const float*)d_in[1];
    const float* p0_k  = (const float*)d_in[2];
    const float* p0_v  = (const float*)d_in[3];
    const float* p0_ea = (const float*)d_in[4];
    const float* p0_eb = (const float*)d_in[5];
    const float* p0_em = (const float*)d_in[6];
    const float* p0_g  = (const float*)d_in[7];
    const float* p0_b  = (const float*)d_in[8];
    const float* p1_q  = (const float*)d_in[9];
    const float* p1_k  = (const float*)d_in[10];
    const float* p1_v  = (const float*)d_in[11];
    const float* p1_ea = (const float*)d_in[12];
    const float* p1_eb = (const float*)d_in[13];
    const float* p1_em = (const float*)d_in[14];
    const float* p1_g  = (const float*)d_in[15];
    const float* p1_b  = (const float*)d_in[16];
    const float* p2_q  = (const float*)d_in[17];
    const float* p2_k  = (const float*)d_in[18];
    const float* p2_v  = (const float*)d_in[19];
    const float* p2_ea = (const float*)d_in[20];
    const float* p2_eb = (const float*)d_in[21];
    const float* p2_em = (const float*)d_in[22];
    const float* p2_g  = (const float*)d_in[23];
    const float* p2_b  = (const float*)d_in[24];
    float* out = (float*)d_out;

    static int smem_set = 0;
    if (!smem_set) {
        cudaFuncSetAttribute(k4_gemm1, cudaFuncAttributeMaxDynamicSharedMemorySize, K4_SMEM);
        smem_set = 1;
    }

    k0_pre<<<1, 256>>>(p0_q, p0_k, p0_v, p0_ea, p0_eb, p0_em,
                       p1_q, p1_k, p1_v, p1_ea, p1_eb, p1_em,
                       p2_q, p2_k, p2_v, p2_ea, p2_eb, p2_em);
    k1_stem0<<<dim3(24, 8, 2), 128>>>(x);
    k3_h1<<<3000, 256>>>(p0_g, p0_b);
    k4_gemm1<<<dim3(141, 12), 256, K4_SMEM>>>();
    k5_attn1<<<dim3(150, 4, 2), 128>>>();
    k8_gemm2<<<dim3(377, 2, 2), 192>>>(p1_g, p1_b);
    k9_attn2<<<dim3(150, 2), 32>>>();
    k11_final<<<dim3(13, 16, 2), 64>>>(out, p2_g, p2_b);
}

// round 4
// speedup vs baseline: 2.3133x; 1.0295x over previous
#include <cuda_runtime.h>
#include <cuda_bf16.h>
#include <math.h>
#include <stdint.h>

// ---------------------------------------------------------------------------
// Static device scratch
// ---------------------------------------------------------------------------
__device__ float d_g0[5*12000];                 // stage0 g-vectors at subsampled positions
__device__ __nv_bfloat16 d_h1h[12000*64];       // stage1 input bf16 hi plane
__device__ __nv_bfloat16 d_h1l[12000*64];       // stage1 input bf16 lo plane
__device__ float d_qkv1[2*6*1504*768];          // stage1 q|k|v padded grid; v cols = 256+o*4+m
__device__ float d_o1raw[2*2*750*128];          // stage1 pre-BN output at subsampled positions
__device__ float d_qkv2[2*2*754*96];            // stage2 q|k|v padded grid; v cols = 32+o*4+m
__device__ float d_out2[2*750*16];              // stage2 pre-BN output

__device__ __nv_bfloat16 d_W1bh[768*64];        // stage1 fused weights, [n][k] bf16 hi
__device__ __nv_bfloat16 d_W1bl[768*64];        // stage1 fused weights, [n][k] bf16 lo
__device__ float d_Wcat2[128*96];
__device__ float d_Weff0[5*64];
__device__ float d_emb1[4*10];
__device__ float d_emb2[4*10];
__device__ float d_C0;

__device__ float d_S0[30];
__device__ float d_sum1[128], d_sumsq1[128];
__device__ float d_sum2[16],  d_sumsq2[16];

__device__ __forceinline__ void mma_bf16(float4& c,
    uint32_t a0, uint32_t a1, uint32_t a2, uint32_t a3,
    uint32_t b0, uint32_t b1)
{
    asm volatile(
        "mma.sync.aligned.m16n8k16.row.col.f32.bf16.bf16.f32 "
        "{%0,%1,%2,%3},{%4,%5,%6,%7},{%8,%9},{%0,%1,%2,%3};"
        : "+f"(c.x), "+f"(c.y), "+f"(c.z), "+f"(c.w)
        : "r"(a0), "r"(a1), "r"(a2), "r"(a3), "r"(b0), "r"(b1));
}

__device__ __forceinline__ void ldsm_x4(uint32_t& r0, uint32_t& r1, uint32_t& r2, uint32_t& r3,
                                        uint32_t addr)
{
    asm volatile("ldmatrix.sync.aligned.m8n8.x4.shared.b16 {%0,%1,%2,%3}, [%4];"
        : "=r"(r0), "=r"(r1), "=r"(r2), "=r"(r3) : "r"(addr));
}

// ---------------------------------------------------------------------------
// K0: precompute embeddings, fused weights, zero stats
// ---------------------------------------------------------------------------
__global__ void k0_pre(const float* p0_q, const float* p0_k, const float* p0_v,
                       const float* p0_ea, const float* p0_eb, const float* p0_em,
                       const float* p1_q, const float* p1_k, const float* p1_v,
                       const float* p1_ea, const float* p1_eb, const float* p1_em,
                       const float* p2_q, const float* p2_k, const float* p2_v,
                       const float* p2_ea, const float* p2_eb, const float* p2_em)
{
    int t = threadIdx.x;
    __shared__ float logit0[4][5], logit1[4][10], logit2[4][10];
    __shared__ float emb0s[4][5];

    if (t == 0) {
        float s = 0.f;
        for (int o = 0; o < 64; o++) s += p0_q[o] * p0_k[o];
        d_C0 = s;
    }
    if (t >= 128 && t < 148) {
        int u = t - 128; int m = u / 5, j = u % 5;
        float la = 0.f, lb = 0.f;
        for (int o = 0; o < 64; o++) {
            la += p0_em[m*64+o] * p0_ea[o];
            lb += p0_em[m*64+o] * p0_eb[o*5+j];
        }
        logit0[m][j] = la + lb;
    }
    if (t < 40) {
        int m = t / 10, kl = t % 10, i = kl / 5, j = kl % 5;
        float la = 0.f, lb = 0.f;
        for (int o = 0; o < 128; o++) {
            la += p1_em[m*128+o] * p1_ea[o*2+i];
            lb += p1_em[m*128+o] * p1_eb[o*5+j];
        }
        logit1[m][kl] = la + lb;
    }
    if (t >= 64 && t < 104) {
        int u = t - 64; int m = u / 10, kl = u % 10, i = kl / 5, j = kl % 5;
        float la = 0.f, lb = 0.f;
        for (int o = 0; o < 16; o++) {
            la += p2_em[m*16+o] * p2_ea[o*2+i];
            lb += p2_em[m*16+o] * p2_eb[o*5+j];
        }
        logit2[m][kl] = la + lb;
    }
    __syncthreads();
    if (t < 5) {
        float mx = -1e30f;
        for (int m = 0; m < 4; m++) mx = fmaxf(mx, logit0[m][t]);
        float e[4], s = 0.f;
        for (int m = 0; m < 4; m++) { e[m] = __expf(logit0[m][t]-mx); s += e[m]; }
        for (int m = 0; m < 4; m++) emb0s[m][t] = e[m] / s;
    }
    if (t >= 32 && t < 42) {
        int kl = t - 32;
        float mx = -1e30f;
        for (int m = 0; m < 4; m++) mx = fmaxf(mx, logit1[m][kl]);
        float e[4], s = 0.f;
        for (int m = 0; m < 4; m++) { e[m] = __expf(logit1[m][kl]-mx); s += e[m]; }
        for (int m = 0; m < 4; m++) d_emb1[m*10+kl] = e[m] / s;
    }
    if (t >= 64 && t < 74) {
        int kl = t - 64;
        float mx = -1e30f;
        for (int m = 0; m < 4; m++) mx = fmaxf(mx, logit2[m][kl]);
        float e[4], s = 0.f;
        for (int m = 0; m < 4; m++) { e[m] = __expf(logit2[m][kl]-mx); s += e[m]; }
        for (int m = 0; m < 4; m++) d_emb2[m*10+kl] = e[m] / s;
    }
    __syncthreads();
    for (int idx = t; idx < 5*64; idx += blockDim.x) {
        int l = idx / 64, o = idx % 64;
        float s = 0.f;
        for (int m = 0; m < 4; m++) s += emb0s[m][l] * p0_v[m*64+o];
        d_Weff0[idx] = s;
    }
    // stage1 fused weights -> bf16 hi/lo, stored [n=768][k=64]
    // col map: [0,128)=q, [128,256)=k, [256,768): o=(j-256)>>2, m=(j-256)&3
    for (int idx = t; idx < 64*768; idx += blockDim.x) {
        int j = idx / 64, c = idx % 64;
        float v;
        if (j < 128)       v = p1_q[c*128 + j];
        else if (j < 256)  v = p1_k[c*128 + (j-128)];
        else { int o = (j-256) >> 2, m = (j-256) & 3; v = p1_v[(m*64+c)*128 + o]; }
        __nv_bfloat16 hi = __float2bfloat16_rn(v);
        d_W1bh[idx] = hi;
        d_W1bl[idx] = __float2bfloat16_rn(v - __bfloat162float(hi));
    }
    // stage2: col map: [0,16)=q, [16,32)=k, [32,96): o=(j-32)>>2, m=(j-32)&3
    for (int idx = t; idx < 128*96; idx += blockDim.x) {
        int c = idx / 96, j = idx % 96;
        float v;
        if (j < 16)       v = p2_q[c*16 + j];
        else if (j < 32)  v = p2_k[c*16 + (j-16)];
        else { int o = (j-32) >> 2, m = (j-32) & 3; v = p2_v[(m*128+c)*16 + o]; }
        d_Wcat2[idx] = v;
    }
    if (t < 30) d_S0[t] = 0.f;
    if (t < 128) { d_sum1[t] = 0.f; d_sumsq1[t] = 0.f; }
    if (t < 16)  { d_sum2[t] = 0.f; d_sumsq2[t] = 0.f; }
}

// ---------------------------------------------------------------------------
// K1: stage0 attention -> g[5] + low-rank BN stats. grid (24,8,2), block 128
// ---------------------------------------------------------------------------
__global__ void k1_stem0(const float* x)
{
    int tid = threadIdx.x;
    int w = blockIdx.x * 128 + tid;
    int h = blockIdx.y, b = blockIdx.z;
    bool valid = (w < 3000);

    float g[5] = {0.f,0.f,0.f,0.f,0.f};
    if (valid) {
        const float* xr = x + (b*8 + h) * 3000;
        float xc = xr[w];
        float C0 = d_C0;
        float xl[5], sc[5];
        float mx = -1e30f;
        #pragma unroll
        for (int l = 0; l < 5; l++) {
            int c = w + l - 2;
            xl[l] = (c >= 0 && c < 3000) ? xr[c] : 0.f;
            sc[l] = xc * xl[l] * C0;
            mx = fmaxf(mx, sc[l]);
        }
        float s = 0.f;
        #pragma unroll
        for (int l = 0; l < 5; l++) { sc[l] = __expf(sc[l]-mx); s += sc[l]; }
        float inv = 1.f / s;
        #pragma unroll
        for (int l = 0; l < 5; l++) g[l] = sc[l] * inv * xl[l];
    }

    float st[20];
    {
        int si = 0;
        #pragma unroll
        for (int l = 0; l < 5; l++) st[si++] = g[l];
        #pragma unroll
        for (int l = 0; l < 5; l++)
            #pragma unroll
            for (int l2 = l; l2 < 5; l2++) st[si++] = g[l]*g[l2];
    }
    #pragma unroll
    for (int i = 0; i < 20; i++)
        #pragma unroll
        for (int off = 16; off; off >>= 1)
            st[i] += __shfl_xor_sync(0xffffffffu, st[i], off);

    __shared__ float red[4][20];
    int lane = tid & 31, wrp = tid >> 5;
    if (lane == 0)
        for (int i = 0; i < 20; i++) red[wrp][i] = st[i];
    __syncthreads();
    if (tid < 20) {
        float v = red[0][tid] + red[1][tid] + red[2][tid] + red[3][tid];
        int slot;
        if (tid < 5) slot = tid;
        else {
            int k = tid - 5, l = 0;
            while (k >= 5 - l) { k -= 5 - l; l++; }
            slot = 5 + l*5 + (l + k);
        }
        atomicAdd(&d_S0[slot], v);
    }

    if (valid && !(h & 1) && !(w & 1)) {
        int p = b*6000 + (h>>1)*1500 + (w>>1);
        #pragma unroll
        for (int l = 0; l < 5; l++) d_g0[l*12000 + p] = g[l];
    }
}

// ---------------------------------------------------------------------------
// K3: stage0 BN (low-rank stats) + ReLU -> h1 bf16 hi/lo. grid 3000, block 256
// ---------------------------------------------------------------------------
__global__ void k3_h1(const float* g0, const float* b0)
{
    __shared__ float sW[5*64];
    __shared__ float sScale[64], sShift[64];
    int tid = threadIdx.x;
    for (int i = tid; i < 320; i += 256) sW[i] = d_Weff0[i];
    __syncthreads();
    if (tid < 64) {
        int c = tid;
        float Wc[5];
        #pragma unroll
        for (int l = 0; l < 5; l++) Wc[l] = sW[l*64 + c];
        float mn = 0.f, mq = 0.f;
        #pragma unroll
        for (int l = 0; l < 5; l++) {
            mn += d_S0[l] * Wc[l];
            #pragma unroll
            for (int l2 = 0; l2 < 5; l2++) {
                int lo = l < l2 ? l : l2, hi = l < l2 ? l2 : l;
                mq += d_S0[5 + lo*5 + hi] * Wc[l] * Wc[l2];
            }
        }
        float n = 48000.f;
        float mean = mn / n;
        float var  = mq / n - mean*mean;
        float sc = g0[c] * rsqrtf(var + 1e-5f);
        sScale[c] = sc;
        sShift[c] = b0[c] - mean * sc;
    }
    __syncthreads();

    int c = tid & 63;
    int p = blockIdx.x * 4 + (tid >> 6);
    float a = 0.f;
    #pragma unroll
    for (int l = 0; l < 5; l++) a += d_g0[l*12000 + p] * sW[l*64 + c];
    float y = fmaxf(fmaf(a, sScale[c], sShift[c]), 0.f);
    __nv_bfloat16 hi = __float2bfloat16_rn(y);
    d_h1h[p*64 + c] = hi;
    d_h1l[p*64 + c] = __float2bfloat16_rn(y - __bfloat162float(hi));
}

// ---------------------------------------------------------------------------
// K4: stage1 qkv GEMM, bf16 3-term hi/lo, m16n8k16 + ldmatrix.
// [18048 x 64] @ [64 x 768]. BM=128, BN=64, 256 threads. grid (141, 12).
// ---------------------------------------------------------------------------
#define K4_SMEM ((128*72 + 128*72 + 64*72 + 64*72) * 2)

__global__ void k4_gemm1()
{
    extern __shared__ __nv_bfloat16 sh[];
    __nv_bfloat16* Ah = sh;               // [128][72]
    __nv_bfloat16* Al = Ah + 128*72;      // [128][72]
    __nv_bfloat16* Bh = Al + 128*72;      // [64 n][72 k]
    __nv_bfloat16* Bl = Bh + 64*72;       // [64 n][72 k]

    int tid = threadIdx.x;
    int rowBase = blockIdx.x * 128;
    int colBase = blockIdx.y * 64;

    // Load A tile (zeros for padded rows)
    {
        int r = tid >> 1;
        int half = (tid & 1) * 32;
        int prow = rowBase + r;
        int b = prow / 9024; int rem = prow % 9024;
        int hp = rem / 1504; int wp = rem % 1504;
        bool valid = (hp >= 1 && hp < 5 && wp >= 2 && wp < 1502);
        __nv_bfloat16* dh = Ah + r*72 + half;
        __nv_bfloat16* dl = Al + r*72 + half;
        if (valid) {
            int pos = ((b*4 + (hp-1))*1500 + (wp-2))*64 + half;
            const uint4* sH = (const uint4*)(d_h1h + pos);
            const uint4* sL = (const uint4*)(d_h1l + pos);
            #pragma unroll
            for (int u = 0; u < 4; u++) {
                ((uint4*)dh)[u] = sH[u];
                ((uint4*)dl)[u] = sL[u];
            }
        } else {
            uint4 z = make_uint4(0,0,0,0);
            #pragma unroll
            for (int u = 0; u < 4; u++) { ((uint4*)dh)[u] = z; ((uint4*)dl)[u] = z; }
        }
    }
    // Load B tile
    {
        int n = tid >> 2;
        int seg = (tid & 3) * 16;
        const uint4* sH = (const uint4*)(d_W1bh + (colBase + n)*64 + seg);
        const uint4* sL = (const uint4*)(d_W1bl + (colBase + n)*64 + seg);
        uint4* dh = (uint4*)(Bh + n*72 + seg);
        uint4* dl = (uint4*)(Bl + n*72 + seg);
        dh[0] = sH[0]; dh[1] = sH[1];
        dl[0] = sL[0]; dl[1] = sL[1];
    }
    __syncthreads();

    int lane = tid & 31, wid = tid >> 5;
    int g = lane >> 2, tg = lane & 3;
    int mr = wid * 16;

    // ldmatrix addresses
    int arow = (lane < 16) ? lane : (lane - 16);
    int acol = (lane < 16) ? 0 : 8;
    uint32_t aAddrH = (uint32_t)__cvta_generic_to_shared(Ah + (mr + arow)*72 + acol);
    uint32_t aAddrL = (uint32_t)__cvta_generic_to_shared(Al + (mr + arow)*72 + acol);

    int brow = (lane & 7) + ((lane >> 4) << 3);
    int bcol = ((lane >> 3) & 1) * 8;
    uint32_t bAddrH[4], bAddrL[4];
    #pragma unroll
    for (int pr = 0; pr < 4; pr++) {
        bAddrH[pr] = (uint32_t)__cvta_generic_to_shared(Bh + (pr*16 + brow)*72 + bcol);
        bAddrL[pr] = (uint32_t)__cvta_generic_to_shared(Bl + (pr*16 + brow)*72 + bcol);
    }

    float4 acc[8];
    #pragma unroll
    for (int i = 0; i < 8; i++) acc[i] = make_float4(0.f,0.f,0.f,0.f);

    #pragma unroll
    for (int ks = 0; ks < 4; ks++) {
        uint32_t koff = ks * 32;   // 16 bf16 = 32 bytes
        uint32_t ah0,ah1,ah2,ah3, al0,al1,al2,al3;
        ldsm_x4(ah0,ah1,ah2,ah3, aAddrH + koff);
        ldsm_x4(al0,al1,al2,al3, aAddrL + koff);

        #pragma unroll
        for (int pr = 0; pr < 4; pr++) {
            uint32_t bh0,bh1,bh2,bh3, bl0,bl1,bl2,bl3;
            ldsm_x4(bh0,bh1,bh2,bh3, bAddrH[pr] + koff);
            ldsm_x4(bl0,bl1,bl2,bl3, bAddrL[pr] + koff);
            mma_bf16(acc[2*pr  ], ah0,ah1,ah2,ah3, bh0,bh1);
            mma_bf16(acc[2*pr  ], ah0,ah1,ah2,ah3, bl0,bl1);
            mma_bf16(acc[2*pr  ], al0,al1,al2,al3, bh0,bh1);
            mma_bf16(acc[2*pr+1], ah0,ah1,ah2,ah3, bh2,bh3);
            mma_bf16(acc[2*pr+1], ah0,ah1,ah2,ah3, bl2,bl3);
            mma_bf16(acc[2*pr+1], al0,al1,al2,al3, bh2,bh3);
        }
    }

    int row0 = rowBase + mr + g;
    #pragma unroll
    for (int nt = 0; nt < 8; nt++) {
        int col = colBase + nt*8 + tg*2;
        *(float2*)&d_qkv1[(size_t)row0*768 + col]     = make_float2(acc[nt].x, acc[nt].y);
        *(float2*)&d_qkv1[(size_t)(row0+8)*768 + col] = make_float2(acc[nt].z, acc[nt].w);
    }
}

// ---------------------------------------------------------------------------
// K5: stage1 attention combine, 10 positions/block, float4 loads,
//     fused BN stats. grid (150, 4, 2), block 256
// ---------------------------------------------------------------------------
__global__ void k5_attn1()
{
    int w0 = blockIdx.x * 10, h = blockIdx.y, b = blockIdx.z;
    int tid = threadIdx.x, lane = tid & 31, wrp = tid >> 5;  // 8 warps
    __shared__ float ssc[10][10];
    __shared__ float cm4[10][40];   // [p][kl*4+m]

    const float* base = d_qkv1 + (size_t)b * 6 * 1504 * 768;

    // scores: 100 (p,kl) pairs over 8 warps
    for (int pair = wrp; pair < 100; pair += 8) {
        int p = pair / 10, kl = pair % 10;
        int i = kl / 5, j = kl % 5;
        const float4* qp = (const float4*)(base + ((h+1)*1504 + (w0+p+2)) * 768);
        const float4* kp = (const float4*)(base + ((h+i)*1504 + (w0+p+j)) * 768 + 128);
        float4 q4 = qp[lane], k4 = kp[lane];
        float s = q4.x*k4.x + q4.y*k4.y + q4.z*k4.z + q4.w*k4.w;
        #pragma unroll
        for (int off = 16; off; off >>= 1) s += __shfl_xor_sync(0xffffffffu, s, off);
        if (lane == 0) ssc[p][kl] = s;
    }
    __syncthreads();
    if (tid < 10) {
        float mx = -1e30f;
        #pragma unroll
        for (int kl = 0; kl < 10; kl++) mx = fmaxf(mx, ssc[tid][kl]);
        float e[10], s = 0.f;
        #pragma unroll
        for (int kl = 0; kl < 10; kl++) { e[kl] = __expf(ssc[tid][kl]-mx); s += e[kl]; }
        float inv = 1.f / s;
        #pragma unroll
        for (int kl = 0; kl < 10; kl++) {
            float a = e[kl] * inv;
            #pragma unroll
            for (int m = 0; m < 4; m++) cm4[tid][kl*4+m] = a * d_emb1[m*10+kl];
        }
    }
    __syncthreads();

    int o = tid & 127;
    int ph = tid >> 7;    // 0/1: which half of positions
    float s1 = 0.f, s2 = 0.f;
    for (int p = ph; p < 10; p += 2) {
        const float* cw = cm4[p];
        float acc = 0.f;
        #pragma unroll
        for (int kl = 0; kl < 10; kl++) {
            int i = kl / 5, j = kl % 5;
            float4 v = *(const float4*)(base + ((h+i)*1504 + (w0+p+j)) * 768 + 256 + o*4);
            acc += cw[kl*4]*v.x + cw[kl*4+1]*v.y + cw[kl*4+2]*v.z + cw[kl*4+3]*v.w;
        }
        s1 += acc; s2 += acc*acc;
        if (!(h & 1) && !((w0+p) & 1))
            d_o1raw[((b*2 + (h>>1))*750 + ((w0+p)>>1))*128 + o] = acc;
    }
    atomicAdd(&d_sum1[o], s1);
    atomicAdd(&d_sumsq1[o], s2);
}

// ---------------------------------------------------------------------------
// K8: stage2 qkv GEMM w/ inline stage1-BN+ReLU. grid (377,2,2), block 192
// ---------------------------------------------------------------------------
__global__ void k8_gemm2(const float* g1, const float* b1)
{
    __shared__ float a[2][128];
    int sub = threadIdx.x / 96;
    int tid = threadIdx.x % 96;
    int wp = blockIdx.x * 2 + sub;
    int hp = blockIdx.y, b = blockIdx.z;
    bool valid = (wp >= 2 && wp < 752);
    for (int i = tid; i < 128; i += 96) {
        float v = 0.f;
        if (valid) {
            float raw = d_o1raw[(((b*2 + hp)*750) + (wp-2))*128 + i];
            float n = 12000.f;
            float mean = d_sum1[i] / n;
            float var  = d_sumsq1[i] / n - mean*mean;
            float sc = g1[i] * rsqrtf(var + 1e-5f);
            v = fmaxf(fmaf(raw, sc, b1[i] - mean*sc), 0.f);
        }
        a[sub][i] = v;
    }
    __syncthreads();
    float acc = 0.f;
    #pragma unroll 8
    for (int c = 0; c < 128; c++) acc += a[sub][c] * d_Wcat2[c*96 + tid];
    d_qkv2[(((b*2 + hp)*754) + wp)*96 + tid] = acc;
}

// ---------------------------------------------------------------------------
// K9: stage2 attention combine, warp per position + fused BN stats.
// grid (188, 2), block 128
// ---------------------------------------------------------------------------
__global__ void k9_attn2()
{
    __shared__ float semb[40];   // [kl*4+m]
    int tid = threadIdx.x;
    if (tid < 40) { int kl = tid >> 2, m = tid & 3; semb[tid] = d_emb2[m*10+kl]; }
    __syncthreads();

    int lane = tid & 31, wrp = tid >> 5;
    int w = blockIdx.x * 4 + wrp, b = blockIdx.y;
    if (w >= 750) return;

    const float* base = d_qkv2 + (size_t)b * 2 * 754 * 96;
    const float* qp = base + (w + 2) * 96;
    float qv = (lane < 16) ? qp[lane] : 0.f;

    float scl[10];
    float mx = -1e30f;
    #pragma unroll
    for (int kl = 0; kl < 10; kl++) {
        int i = kl / 5, j = kl % 5;
        const float* kp = base + (i*754 + (w+j))*96 + 16;
        float pr = (lane < 16) ? qv * kp[lane] : 0.f;
        #pragma unroll
        for (int off = 8; off; off >>= 1) pr += __shfl_xor_sync(0xffffffffu, pr, off);
        scl[kl] = pr;
        mx = fmaxf(mx, pr);
    }
    float s = 0.f;
    #pragma unroll
    for (int kl = 0; kl < 10; kl++) { scl[kl] = __expf(scl[kl]-mx); s += scl[kl]; }
    float inv = 1.f / s;
    if (lane < 16) {
        float acc = 0.f;
        #pragma unroll
        for (int kl = 0; kl < 10; kl++) {
            int i = kl / 5, j = kl % 5;
            float4 v = *(const float4*)(base + (i*754 + (w+j))*96 + 32 + lane*4);
            float aw = scl[kl] * inv;
            acc += aw * (semb[kl*4]*v.x + semb[kl*4+1]*v.y + semb[kl*4+2]*v.z + semb[kl*4+3]*v.w);
        }
        d_out2[(b*750 + w)*16 + lane] = acc;
        atomicAdd(&d_sum2[lane], acc);
        atomicAdd(&d_sumsq2[lane], acc*acc);
    }
}

// ---------------------------------------------------------------------------
// K11: stage2 BN + ReLU + AvgPool(1,56) -> out. grid (13,16,2), block 64
// ---------------------------------------------------------------------------
__global__ void k11_final(float* out, const float* g2, const float* b2)
{
    int n = blockIdx.x, c = blockIdx.y, b = blockIdx.z;
    int t = threadIdx.x;
    float nn = 1500.f;
    float mean = d_sum2[c] / nn;
    float var  = d_sumsq2[c] / nn - mean*mean;
    float sc = g2[c] * rsqrtf(var + 1e-5f);
    float sf = b2[c] - mean * sc;

    float v = 0.f;
    if (t < 56) {
        float raw = d_out2[(b*750 + n*56 + t)*16 + c];
        v = fmaxf(fmaf(raw, sc, sf), 0.f);
    }
    __shared__ float shm[64];
    shm[t] = v;
    __syncthreads();
    for (int st = 32; st; st >>= 1) {
        if (t < st) shm[t] += shm[t+st];
        __syncthreads();
    }
    if (t == 0) out[(b*16 + c)*13 + n] = shm[0] * (1.f/56.f);
}

// ---------------------------------------------------------------------------
extern "C" void kernel_launch(void* const* d_in, const int* in_sizes, int n_in,
                              void* d_out, int out_size)
{
    const float* x     = (const float*)d_in[0];
    const float* p0_q  = (const float*)d_in[1];
    const float* p0_k  = (const float*)d_in[2];
    const float* p0_v  = (const float*)d_in[3];
    const float* p0_ea = (const float*)d_in[4];
    const float* p0_eb = (const float*)d_in[5];
    const float* p0_em = (const float*)d_in[6];
    const float* p0_g  = (const float*)d_in[7];
    const float* p0_b  = (const float*)d_in[8];
    const float* p1_q  = (const float*)d_in[9];
    const float* p1_k  = (const float*)d_in[10];
    const float* p1_v  = (const float*)d_in[11];
    const float* p1_ea = (const float*)d_in[12];
    const float* p1_eb = (const float*)d_in[13];
    const float* p1_em = (const float*)d_in[14];
    const float* p1_g  = (const float*)d_in[15];
    const float* p1_b  = (const float*)d_in[16];
    const float* p2_q  = (const float*)d_in[17];
    const float* p2_k  = (const float*)d_in[18];
    const float* p2_v  = (const float*)d_in[19];
    const float* p2_ea = (const float*)d_in[20];
    const float* p2_eb = (const float*)d_in[21];
    const float* p2_em = (const float*)d_in[22];
    const float* p2_g  = (const float*)d_in[23];
    const float* p2_b  = (const float*)d_in[24];
    float* out = (float*)d_out;

    static int smem_set = 0;
    if (!smem_set) {
        cudaFuncSetAttribute(k4_gemm1, cudaFuncAttributeMaxDynamicSharedMemorySize, K4_SMEM);
        smem_set = 1;
    }

    k0_pre<<<1, 256>>>(p0_q, p0_k, p0_v, p0_ea, p0_eb, p0_em,
                       p1_q, p1_k, p1_v, p1_ea, p1_eb, p1_em,
                       p2_q, p2_k, p2_v, p2_ea, p2_eb, p2_em);
    k1_stem0<<<dim3(24, 8, 2), 128>>>(x);
    k3_h1<<<3000, 256>>>(p0_g, p0_b);
    k4_gemm1<<<dim3(141, 12), 256, K4_SMEM>>>();
    k5_attn1<<<dim3(150, 4, 2), 256>>>();
    k8_gemm2<<<dim3(377, 2, 2), 192>>>(p1_g, p1_b);
    k9_attn2<<<dim3(188, 2), 128>>>();
    k11_final<<<dim3(13, 16, 2), 64>>>(out, p2_g, p2_b);
}

// round 5
// speedup vs baseline: 2.3801x; 1.0289x over previous
#include <cuda_runtime.h>
#include <cuda_bf16.h>
#include <math.h>
#include <stdint.h>

// ---------------------------------------------------------------------------
// Static device scratch
// ---------------------------------------------------------------------------
__device__ float d_g0[5*12000];                 // stage0 g-vectors at subsampled positions
__device__ __nv_bfloat16 d_h1h[12000*64];       // stage1 input bf16 hi plane
__device__ __nv_bfloat16 d_h1l[12000*64];       // stage1 input bf16 lo plane
__device__ float d_qkv1[2*6*1504*768];          // stage1 q|k|v padded grid; v cols = 256+o*4+m
__device__ float d_o1raw[2*2*750*128];          // stage1 pre-BN output at subsampled positions
__device__ float d_qkv2[2*2*754*96];            // stage2 q|k|v padded grid; v cols = 32+o*4+m
__device__ float d_out2[2*750*16];              // stage2 pre-BN output

__device__ __nv_bfloat16 d_W1bh[768*64];        // stage1 fused weights, [n][k] bf16 hi
__device__ __nv_bfloat16 d_W1bl[768*64];        // stage1 fused weights, [n][k] bf16 lo
__device__ float d_Wcat2[128*96];
__device__ float d_Weff0[5*64];
__device__ float d_emb1[4*10];
__device__ float d_emb2[4*10];
__device__ float d_C0;

__device__ float d_S0[30];
__device__ float d_sum1[128], d_sumsq1[128];
__device__ float d_sum2[16],  d_sumsq2[16];

__device__ __forceinline__ void mma_bf16(float4& c,
    uint32_t a0, uint32_t a1, uint32_t a2, uint32_t a3,
    uint32_t b0, uint32_t b1)
{
    asm volatile(
        "mma.sync.aligned.m16n8k16.row.col.f32.bf16.bf16.f32 "
        "{%0,%1,%2,%3},{%4,%5,%6,%7},{%8,%9},{%0,%1,%2,%3};"
        : "+f"(c.x), "+f"(c.y), "+f"(c.z), "+f"(c.w)
        : "r"(a0), "r"(a1), "r"(a2), "r"(a3), "r"(b0), "r"(b1));
}

__device__ __forceinline__ void ldsm_x4(uint32_t& r0, uint32_t& r1, uint32_t& r2, uint32_t& r3,
                                        uint32_t addr)
{
    asm volatile("ldmatrix.sync.aligned.m8n8.x4.shared.b16 {%0,%1,%2,%3}, [%4];"
        : "=r"(r0), "=r"(r1), "=r"(r2), "=r"(r3) : "r"(addr));
}

// ---------------------------------------------------------------------------
// K0: precompute embeddings, fused weights, zero stats
// ---------------------------------------------------------------------------
__global__ void k0_pre(const float* p0_q, const float* p0_k, const float* p0_v,
                       const float* p0_ea, const float* p0_eb, const float* p0_em,
                       const float* p1_q, const float* p1_k, const float* p1_v,
                       const float* p1_ea, const float* p1_eb, const float* p1_em,
                       const float* p2_q, const float* p2_k, const float* p2_v,
                       const float* p2_ea, const float* p2_eb, const float* p2_em)
{
    int t = threadIdx.x;
    __shared__ float logit0[4][5], logit1[4][10], logit2[4][10];
    __shared__ float emb0s[4][5];

    if (t == 0) {
        float s = 0.f;
        for (int o = 0; o < 64; o++) s += p0_q[o] * p0_k[o];
        d_C0 = s;
    }
    if (t >= 128 && t < 148) {
        int u = t - 128; int m = u / 5, j = u % 5;
        float la = 0.f, lb = 0.f;
        for (int o = 0; o < 64; o++) {
            la += p0_em[m*64+o] * p0_ea[o];
            lb += p0_em[m*64+o] * p0_eb[o*5+j];
        }
        logit0[m][j] = la + lb;
    }
    if (t < 40) {
        int m = t / 10, kl = t % 10, i = kl / 5, j = kl % 5;
        float la = 0.f, lb = 0.f;
        for (int o = 0; o < 128; o++) {
            la += p1_em[m*128+o] * p1_ea[o*2+i];
            lb += p1_em[m*128+o] * p1_eb[o*5+j];
        }
        logit1[m][kl] = la + lb;
    }
    if (t >= 64 && t < 104) {
        int u = t - 64; int m = u / 10, kl = u % 10, i = kl / 5, j = kl % 5;
        float la = 0.f, lb = 0.f;
        for (int o = 0; o < 16; o++) {
            la += p2_em[m*16+o] * p2_ea[o*2+i];
            lb += p2_em[m*16+o] * p2_eb[o*5+j];
        }
        logit2[m][kl] = la + lb;
    }
    __syncthreads();
    if (t < 5) {
        float mx = -1e30f;
        for (int m = 0; m < 4; m++) mx = fmaxf(mx, logit0[m][t]);
        float e[4], s = 0.f;
        for (int m = 0; m < 4; m++) { e[m] = __expf(logit0[m][t]-mx); s += e[m]; }
        for (int m = 0; m < 4; m++) emb0s[m][t] = e[m] / s;
    }
    if (t >= 32 && t < 42) {
        int kl = t - 32;
        float mx = -1e30f;
        for (int m = 0; m < 4; m++) mx = fmaxf(mx, logit1[m][kl]);
        float e[4], s = 0.f;
        for (int m = 0; m < 4; m++) { e[m] = __expf(logit1[m][kl]-mx); s += e[m]; }
        for (int m = 0; m < 4; m++) d_emb1[m*10+kl] = e[m] / s;
    }
    if (t >= 64 && t < 74) {
        int kl = t - 64;
        float mx = -1e30f;
        for (int m = 0; m < 4; m++) mx = fmaxf(mx, logit2[m][kl]);
        float e[4], s = 0.f;
        for (int m = 0; m < 4; m++) { e[m] = __expf(logit2[m][kl]-mx); s += e[m]; }
        for (int m = 0; m < 4; m++) d_emb2[m*10+kl] = e[m] / s;
    }
    __syncthreads();
    for (int idx = t; idx < 5*64; idx += blockDim.x) {
        int l = idx / 64, o = idx % 64;
        float s = 0.f;
        for (int m = 0; m < 4; m++) s += emb0s[m][l] * p0_v[m*64+o];
        d_Weff0[idx] = s;
    }
    // stage1 fused weights -> bf16 hi/lo, stored [n=768][k=64]
    for (int idx = t; idx < 64*768; idx += blockDim.x) {
        int j = idx / 64, c = idx % 64;
        float v;
        if (j < 128)       v = p1_q[c*128 + j];
        else if (j < 256)  v = p1_k[c*128 + (j-128)];
        else { int o = (j-256) >> 2, m = (j-256) & 3; v = p1_v[(m*64+c)*128 + o]; }
        __nv_bfloat16 hi = __float2bfloat16_rn(v);
        d_W1bh[idx] = hi;
        d_W1bl[idx] = __float2bfloat16_rn(v - __bfloat162float(hi));
    }
    for (int idx = t; idx < 128*96; idx += blockDim.x) {
        int c = idx / 96, j = idx % 96;
        float v;
        if (j < 16)       v = p2_q[c*16 + j];
        else if (j < 32)  v = p2_k[c*16 + (j-16)];
        else { int o = (j-32) >> 2, m = (j-32) & 3; v = p2_v[(m*128+c)*16 + o]; }
        d_Wcat2[idx] = v;
    }
    if (t < 30) d_S0[t] = 0.f;
    if (t < 128) { d_sum1[t] = 0.f; d_sumsq1[t] = 0.f; }
    if (t < 16)  { d_sum2[t] = 0.f; d_sumsq2[t] = 0.f; }
}

// ---------------------------------------------------------------------------
// K1: stage0 attention -> g[5] + low-rank BN stats. grid (24,8,2), block 128
// ---------------------------------------------------------------------------
__global__ void k1_stem0(const float* x)
{
    int tid = threadIdx.x;
    int w = blockIdx.x * 128 + tid;
    int h = blockIdx.y, b = blockIdx.z;
    bool valid = (w < 3000);

    float g[5] = {0.f,0.f,0.f,0.f,0.f};
    if (valid) {
        const float* xr = x + (b*8 + h) * 3000;
        float xc = xr[w];
        float C0 = d_C0;
        float xl[5], sc[5];
        float mx = -1e30f;
        #pragma unroll
        for (int l = 0; l < 5; l++) {
            int c = w + l - 2;
            xl[l] = (c >= 0 && c < 3000) ? xr[c] : 0.f;
            sc[l] = xc * xl[l] * C0;
            mx = fmaxf(mx, sc[l]);
        }
        float s = 0.f;
        #pragma unroll
        for (int l = 0; l < 5; l++) { sc[l] = __expf(sc[l]-mx); s += sc[l]; }
        float inv = 1.f / s;
        #pragma unroll
        for (int l = 0; l < 5; l++) g[l] = sc[l] * inv * xl[l];
    }

    float st[20];
    {
        int si = 0;
        #pragma unroll
        for (int l = 0; l < 5; l++) st[si++] = g[l];
        #pragma unroll
        for (int l = 0; l < 5; l++)
            #pragma unroll
            for (int l2 = l; l2 < 5; l2++) st[si++] = g[l]*g[l2];
    }
    #pragma unroll
    for (int i = 0; i < 20; i++)
        #pragma unroll
        for (int off = 16; off; off >>= 1)
            st[i] += __shfl_xor_sync(0xffffffffu, st[i], off);

    __shared__ float red[4][20];
    int lane = tid & 31, wrp = tid >> 5;
    if (lane == 0)
        for (int i = 0; i < 20; i++) red[wrp][i] = st[i];
    __syncthreads();
    if (tid < 20) {
        float v = red[0][tid] + red[1][tid] + red[2][tid] + red[3][tid];
        int slot;
        if (tid < 5) slot = tid;
        else {
            int k = tid - 5, l = 0;
            while (k >= 5 - l) { k -= 5 - l; l++; }
            slot = 5 + l*5 + (l + k);
        }
        atomicAdd(&d_S0[slot], v);
    }

    if (valid && !(h & 1) && !(w & 1)) {
        int p = b*6000 + (h>>1)*1500 + (w>>1);
        #pragma unroll
        for (int l = 0; l < 5; l++) d_g0[l*12000 + p] = g[l];
    }
}

// ---------------------------------------------------------------------------
// K3: stage0 BN (low-rank stats) + ReLU -> h1 bf16 hi/lo. grid 3000, block 256
// ---------------------------------------------------------------------------
__global__ void k3_h1(const float* g0, const float* b0)
{
    __shared__ float sW[5*64];
    __shared__ float sScale[64], sShift[64];
    int tid = threadIdx.x;
    for (int i = tid; i < 320; i += 256) sW[i] = d_Weff0[i];
    __syncthreads();
    if (tid < 64) {
        int c = tid;
        float Wc[5];
        #pragma unroll
        for (int l = 0; l < 5; l++) Wc[l] = sW[l*64 + c];
        float mn = 0.f, mq = 0.f;
        #pragma unroll
        for (int l = 0; l < 5; l++) {
            mn += d_S0[l] * Wc[l];
            #pragma unroll
            for (int l2 = 0; l2 < 5; l2++) {
                int lo = l < l2 ? l : l2, hi = l < l2 ? l2 : l;
                mq += d_S0[5 + lo*5 + hi] * Wc[l] * Wc[l2];
            }
        }
        float n = 48000.f;
        float mean = mn / n;
        float var  = mq / n - mean*mean;
        float sc = g0[c] * rsqrtf(var + 1e-5f);
        sScale[c] = sc;
        sShift[c] = b0[c] - mean * sc;
    }
    __syncthreads();

    int c = tid & 63;
    int p = blockIdx.x * 4 + (tid >> 6);
    float a = 0.f;
    #pragma unroll
    for (int l = 0; l < 5; l++) a += d_g0[l*12000 + p] * sW[l*64 + c];
    float y = fmaxf(fmaf(a, sScale[c], sShift[c]), 0.f);
    __nv_bfloat16 hi = __float2bfloat16_rn(y);
    d_h1h[p*64 + c] = hi;
    d_h1l[p*64 + c] = __float2bfloat16_rn(y - __bfloat162float(hi));
}

// ---------------------------------------------------------------------------
// K4: stage1 qkv GEMM, only real rows hp in [1,4]: M'=12032.
// bf16 3-term hi/lo, m16n8k16 + ldmatrix, 4x2 warp layout (Mw=32,Nw=32).
// Each block also zero-fills its share of the hp=0 pad rows of qkv1.
// grid (94, 12), block 256.
// ---------------------------------------------------------------------------
#define K4_SMEM ((128*72 + 128*72 + 64*72 + 64*72) * 2)

__global__ void k4_gemm1()
{
    extern __shared__ __nv_bfloat16 sh[];
    __nv_bfloat16* Ah = sh;               // [128][72]
    __nv_bfloat16* Al = Ah + 128*72;      // [128][72]
    __nv_bfloat16* Bh = Al + 128*72;      // [64 n][72 k]
    __nv_bfloat16* Bl = Bh + 64*72;       // [64 n][72 k]

    int tid = threadIdx.x;
    int rowBase = blockIdx.x * 128;       // compacted row space [0,12032)
    int colBase = blockIdx.y * 64;

    // Zero-fill share of hp=0 pad rows: 577536 float4 over 1128 blocks = 512 each
    {
        int blockId = blockIdx.y * 94 + blockIdx.x;
        float4 z4 = make_float4(0.f,0.f,0.f,0.f);
        #pragma unroll
        for (int u = 0; u < 2; u++) {
            int f4idx = blockId*512 + u*256 + tid;
            int fidx = f4idx * 4;
            int row = fidx / 768, col = fidx % 768;   // row in [0,3008)
            int b = row >= 1504;
            int wp = row - b*1504;
            *(float4*)&d_qkv1[((size_t)b*9024 + wp)*768 + col] = z4;
        }
    }

    // Load A tile (zeros for w-pad columns; hp always in [1,4])
    {
        int r = tid >> 1;
        int half = (tid & 1) * 32;
        int prow = rowBase + r;
        int b = prow / 6016; int rem = prow % 6016;
        int hp = 1 + rem / 1504; int wp = rem % 1504;
        bool valid = (wp >= 2 && wp < 1502);
        __nv_bfloat16* dh = Ah + r*72 + half;
        __nv_bfloat16* dl = Al + r*72 + half;
        if (valid) {
            int pos = ((b*4 + (hp-1))*1500 + (wp-2))*64 + half;
            const uint4* sH = (const uint4*)(d_h1h + pos);
            const uint4* sL = (const uint4*)(d_h1l + pos);
            #pragma unroll
            for (int u = 0; u < 4; u++) {
                ((uint4*)dh)[u] = sH[u];
                ((uint4*)dl)[u] = sL[u];
            }
        } else {
            uint4 z = make_uint4(0,0,0,0);
            #pragma unroll
            for (int u = 0; u < 4; u++) { ((uint4*)dh)[u] = z; ((uint4*)dl)[u] = z; }
        }
    }
    // Load B tile
    {
        int n = tid >> 2;
        int seg = (tid & 3) * 16;
        const uint4* sH = (const uint4*)(d_W1bh + (colBase + n)*64 + seg);
        const uint4* sL = (const uint4*)(d_W1bl + (colBase + n)*64 + seg);
        uint4* dh = (uint4*)(Bh + n*72 + seg);
        uint4* dl = (uint4*)(Bl + n*72 + seg);
        dh[0] = sH[0]; dh[1] = sH[1];
        dl[0] = sL[0]; dl[1] = sL[1];
    }
    __syncthreads();

    int lane = tid & 31, wid = tid >> 5;
    int g = lane >> 2, tg = lane & 3;
    int mr   = (wid >> 1) * 32;     // 4 M-groups of 32 rows
    int ncol = (wid & 1) * 32;      // 2 N-halves of 32 cols

    // ldmatrix addresses
    int arow = (lane < 16) ? lane : (lane - 16);
    int acol = (lane < 16) ? 0 : 8;
    uint32_t aAddrH[2], aAddrL[2];
    #pragma unroll
    for (int mt = 0; mt < 2; mt++) {
        aAddrH[mt] = (uint32_t)__cvta_generic_to_shared(Ah + (mr + mt*16 + arow)*72 + acol);
        aAddrL[mt] = (uint32_t)__cvta_generic_to_shared(Al + (mr + mt*16 + arow)*72 + acol);
    }
    int brow = (lane & 7) + ((lane >> 4) << 3);
    int bcol = ((lane >> 3) & 1) * 8;
    uint32_t bAddrH[2], bAddrL[2];
    #pragma unroll
    for (int pr = 0; pr < 2; pr++) {
        bAddrH[pr] = (uint32_t)__cvta_generic_to_shared(Bh + (ncol + pr*16 + brow)*72 + bcol);
        bAddrL[pr] = (uint32_t)__cvta_generic_to_shared(Bl + (ncol + pr*16 + brow)*72 + bcol);
    }

    float4 acc[2][4];
    #pragma unroll
    for (int i = 0; i < 2; i++)
        #pragma unroll
        for (int j = 0; j < 4; j++) acc[i][j] = make_float4(0.f,0.f,0.f,0.f);

    #pragma unroll
    for (int ks = 0; ks < 4; ks++) {
        uint32_t koff = ks * 32;   // 16 bf16 = 32 bytes
        uint32_t ah[2][4], al[2][4], bh[2][4], bl[2][4];
        #pragma unroll
        for (int mt = 0; mt < 2; mt++) {
            ldsm_x4(ah[mt][0],ah[mt][1],ah[mt][2],ah[mt][3], aAddrH[mt] + koff);
            ldsm_x4(al[mt][0],al[mt][1],al[mt][2],al[mt][3], aAddrL[mt] + koff);
        }
        #pragma unroll
        for (int pr = 0; pr < 2; pr++) {
            ldsm_x4(bh[pr][0],bh[pr][1],bh[pr][2],bh[pr][3], bAddrH[pr] + koff);
            ldsm_x4(bl[pr][0],bl[pr][1],bl[pr][2],bl[pr][3], bAddrL[pr] + koff);
        }
        #pragma unroll
        for (int mt = 0; mt < 2; mt++)
            #pragma unroll
            for (int pr = 0; pr < 2; pr++) {
                mma_bf16(acc[mt][2*pr  ], ah[mt][0],ah[mt][1],ah[mt][2],ah[mt][3], bh[pr][0],bh[pr][1]);
                mma_bf16(acc[mt][2*pr  ], ah[mt][0],ah[mt][1],ah[mt][2],ah[mt][3], bl[pr][0],bl[pr][1]);
                mma_bf16(acc[mt][2*pr  ], al[mt][0],al[mt][1],al[mt][2],al[mt][3], bh[pr][0],bh[pr][1]);
                mma_bf16(acc[mt][2*pr+1], ah[mt][0],ah[mt][1],ah[mt][2],ah[mt][3], bh[pr][2],bh[pr][3]);
                mma_bf16(acc[mt][2*pr+1], ah[mt][0],ah[mt][1],ah[mt][2],ah[mt][3], bl[pr][2],bl[pr][3]);
                mma_bf16(acc[mt][2*pr+1], al[mt][0],al[mt][1],al[mt][2],al[mt][3], bh[pr][2],bh[pr][3]);
            }
    }

    // Store: map compacted rows back to padded grid
    #pragma unroll
    for (int mt = 0; mt < 2; mt++) {
        #pragma unroll
        for (int half = 0; half < 2; half++) {
            int prow = rowBase + mr + mt*16 + half*8 + g;
            int b = prow / 6016; int rem = prow % 6016;
            int hp = 1 + rem / 1504; int wp = rem % 1504;
            size_t orow = (size_t)(b*6 + hp)*1504 + wp;
            #pragma unroll
            for (int j = 0; j < 4; j++) {
                int col = colBase + ncol + j*8 + tg*2;
                float2 v = half ? make_float2(acc[mt][j].z, acc[mt][j].w)
                                : make_float2(acc[mt][j].x, acc[mt][j].y);
                *(float2*)&d_qkv1[orow*768 + col] = v;
            }
        }
    }
}

// ---------------------------------------------------------------------------
// K5: stage1 attention combine, 10 positions/block, 512 threads,
//     fused BN stats. grid (150, 4, 2)
// ---------------------------------------------------------------------------
__global__ void k5_attn1()
{
    int w0 = blockIdx.x * 10, h = blockIdx.y, b = blockIdx.z;
    int tid = threadIdx.x, lane = tid & 31, wrp = tid >> 5;  // 16 warps
    __shared__ float ssc[10][10];
    __shared__ float cm4[10][40];   // [p][kl*4+m]

    const float* base = d_qkv1 + (size_t)b * 6 * 1504 * 768;

    // scores: 100 (p,kl) pairs over 16 warps
    for (int pair = wrp; pair < 100; pair += 16) {
        int p = pair / 10, kl = pair % 10;
        int i = kl / 5, j = kl % 5;
        const float4* qp = (const float4*)(base + ((h+1)*1504 + (w0+p+2)) * 768);
        const float4* kp = (const float4*)(base + ((h+i)*1504 + (w0+p+j)) * 768 + 128);
        float4 q4 = qp[lane], k4 = kp[lane];
        float s = q4.x*k4.x + q4.y*k4.y + q4.z*k4.z + q4.w*k4.w;
        #pragma unroll
        for (int off = 16; off; off >>= 1) s += __shfl_xor_sync(0xffffffffu, s, off);
        if (lane == 0) ssc[p][kl] = s;
    }
    __syncthreads();
    if (tid < 10) {
        float mx = -1e30f;
        #pragma unroll
        for (int kl = 0; kl < 10; kl++) mx = fmaxf(mx, ssc[tid][kl]);
        float e[10], s = 0.f;
        #pragma unroll
        for (int kl = 0; kl < 10; kl++) { e[kl] = __expf(ssc[tid][kl]-mx); s += e[kl]; }
        float inv = 1.f / s;
        #pragma unroll
        for (int kl = 0; kl < 10; kl++) {
            float a = e[kl] * inv;
            #pragma unroll
            for (int m = 0; m < 4; m++) cm4[tid][kl*4+m] = a * d_emb1[m*10+kl];
        }
    }
    __syncthreads();

    int o = tid & 127;
    int ph = tid >> 7;    // 0..3: position quarter
    float s1 = 0.f, s2 = 0.f;
    for (int p = ph; p < 10; p += 4) {
        const float* cw = cm4[p];
        float acc = 0.f;
        #pragma unroll
        for (int kl = 0; kl < 10; kl++) {
            int i = kl / 5, j = kl % 5;
            float4 v = *(const float4*)(base + ((h+i)*1504 + (w0+p+j)) * 768 + 256 + o*4);
            acc += cw[kl*4]*v.x + cw[kl*4+1]*v.y + cw[kl*4+2]*v.z + cw[kl*4+3]*v.w;
        }
        s1 += acc; s2 += acc*acc;
        if (!(h & 1) && !((w0+p) & 1))
            d_o1raw[((b*2 + (h>>1))*750 + ((w0+p)>>1))*128 + o] = acc;
    }
    atomicAdd(&d_sum1[o], s1);
    atomicAdd(&d_sumsq1[o], s2);
}

// ---------------------------------------------------------------------------
// K8: stage2 qkv GEMM w/ inline stage1-BN+ReLU. grid (377,2,2), block 192
// ---------------------------------------------------------------------------
__global__ void k8_gemm2(const float* g1, const float* b1)
{
    __shared__ float a[2][128];
    __shared__ float sScale[128], sShift[128];
    int t = threadIdx.x;
    if (t < 128) {
        float n = 12000.f;
        float mean = d_sum1[t] / n;
        float var  = d_sumsq1[t] / n - mean*mean;
        float sc = g1[t] * rsqrtf(var + 1e-5f);
        sScale[t] = sc;
        sShift[t] = b1[t] - mean*sc;
    }
    __syncthreads();

    int sub = t / 96;
    int tid = t % 96;
    int wp = blockIdx.x * 2 + sub;
    int hp = blockIdx.y, b = blockIdx.z;
    bool valid = (wp >= 2 && wp < 752);
    for (int i = tid; i < 128; i += 96) {
        float v = 0.f;
        if (valid) {
            float raw = d_o1raw[(((b*2 + hp)*750) + (wp-2))*128 + i];
            v = fmaxf(fmaf(raw, sScale[i], sShift[i]), 0.f);
        }
        a[sub][i] = v;
    }
    __syncthreads();
    float acc = 0.f;
    #pragma unroll 8
    for (int c = 0; c < 128; c++) acc += a[sub][c] * d_Wcat2[c*96 + tid];
    d_qkv2[(((b*2 + hp)*754) + wp)*96 + tid] = acc;
}

// ---------------------------------------------------------------------------
// K9: stage2 attention combine, warp per position + fused BN stats.
// grid (188, 2), block 128
// ---------------------------------------------------------------------------
__global__ void k9_attn2()
{
    __shared__ float semb[40];   // [kl*4+m]
    int tid = threadIdx.x;
    if (tid < 40) { int kl = tid >> 2, m = tid & 3; semb[tid] = d_emb2[m*10+kl]; }
    __syncthreads();

    int lane = tid & 31, wrp = tid >> 5;
    int w = blockIdx.x * 4 + wrp, b = blockIdx.y;
    if (w >= 750) return;

    const float* base = d_qkv2 + (size_t)b * 2 * 754 * 96;
    const float* qp = base + (w + 2) * 96;
    float qv = (lane < 16) ? qp[lane] : 0.f;

    float scl[10];
    float mx = -1e30f;
    #pragma unroll
    for (int kl = 0; kl < 10; kl++) {
        int i = kl / 5, j = kl % 5;
        const float* kp = base + (i*754 + (w+j))*96 + 16;
        float pr = (lane < 16) ? qv * kp[lane] : 0.f;
        #pragma unroll
        for (int off = 8; off; off >>= 1) pr += __shfl_xor_sync(0xffffffffu, pr, off);
        scl[kl] = pr;
        mx = fmaxf(mx, pr);
    }
    float s = 0.f;
    #pragma unroll
    for (int kl = 0; kl < 10; kl++) { scl[kl] = __expf(scl[kl]-mx); s += scl[kl]; }
    float inv = 1.f / s;
    if (lane < 16) {
        float acc = 0.f;
        #pragma unroll
        for (int kl = 0; kl < 10; kl++) {
            int i = kl / 5, j = kl % 5;
            float4 v = *(const float4*)(base + (i*754 + (w+j))*96 + 32 + lane*4);
            float aw = scl[kl] * inv;
            acc += aw * (semb[kl*4]*v.x + semb[kl*4+1]*v.y + semb[kl*4+2]*v.z + semb[kl*4+3]*v.w);
        }
        d_out2[(b*750 + w)*16 + lane] = acc;
        atomicAdd(&d_sum2[lane], acc);
        atomicAdd(&d_sumsq2[lane], acc*acc);
    }
}

// ---------------------------------------------------------------------------
// K11: stage2 BN + ReLU + AvgPool(1,56) -> out. grid (13,16,2), block 64
// ---------------------------------------------------------------------------
__global__ void k11_final(float* out, const float* g2, const float* b2)
{
    int n = blockIdx.x, c = blockIdx.y, b = blockIdx.z;
    int t = threadIdx.x;
    float nn = 1500.f;
    float mean = d_sum2[c] / nn;
    float var  = d_sumsq2[c] / nn - mean*mean;
    float sc = g2[c] * rsqrtf(var + 1e-5f);
    float sf = b2[c] - mean * sc;

    float v = 0.f;
    if (t < 56) {
        float raw = d_out2[(b*750 + n*56 + t)*16 + c];
        v = fmaxf(fmaf(raw, sc, sf), 0.f);
    }
    __shared__ float shm[64];
    shm[t] = v;
    __syncthreads();
    for (int st = 32; st; st >>= 1) {
        if (t < st) shm[t] += shm[t+st];
        __syncthreads();
    }
    if (t == 0) out[(b*16 + c)*13 + n] = shm[0] * (1.f/56.f);
}

// ---------------------------------------------------------------------------
extern "C" void kernel_launch(void* const* d_in, const int* in_sizes, int n_in,
                              void* d_out, int out_size)
{
    const float* x     = (const float*)d_in[0];
    const float* p0_q  = (const float*)d_in[1];
    const float* p0_k  = (const float*)d_in[2];
    const float* p0_v  = (const float*)d_in[3];
    const float* p0_ea = (const float*)d_in[4];
    const float* p0_eb = (const float*)d_in[5];
    const float* p0_em = (const float*)d_in[6];
    const float* p0_g  = (const float*)d_in[7];
    const float* p0_b  = (const float*)d_in[8];
    const float* p1_q  = (const float*)d_in[9];
    const float* p1_k  = (const float*)d_in[10];
    const float* p1_v  = (const float*)d_in[11];
    const float* p1_ea = (const float*)d_in[12];
    const float* p1_eb = (const float*)d_in[13];
    const float* p1_em = (const float*)d_in[14];
    const float* p1_g  = (const float*)d_in[15];
    const float* p1_b  = (const float*)d_in[16];
    const float* p2_q  = (const float*)d_in[17];
    const float* p2_k  = (const float*)d_in[18];
    const float* p2_v  = (const float*)d_in[19];
    const float* p2_ea = (const float*)d_in[20];
    const float* p2_eb = (const float*)d_in[21];
    const float* p2_em = (const float*)d_in[22];
    const float* p2_g  = (const float*)d_in[23];
    const float* p2_b  = (const float*)d_in[24];
    float* out = (float*)d_out;

    static int smem_set = 0;
    if (!smem_set) {
        cudaFuncSetAttribute(k4_gemm1, cudaFuncAttributeMaxDynamicSharedMemorySize, K4_SMEM);
        smem_set = 1;
    }

    k0_pre<<<1, 256>>>(p0_q, p0_k, p0_v, p0_ea, p0_eb, p0_em,
                       p1_q, p1_k, p1_v, p1_ea, p1_eb, p1_em,
                       p2_q, p2_k, p2_v, p2_ea, p2_eb, p2_em);
    k1_stem0<<<dim3(24, 8, 2), 128>>>(x);
    k3_h1<<<3000, 256>>>(p0_g, p0_b);
    k4_gemm1<<<dim3(94, 12), 256, K4_SMEM>>>();
    k5_attn1<<<dim3(150, 4, 2), 512>>>();
    k8_gemm2<<<dim3(377, 2, 2), 192>>>(p1_g, p1_b);
    k9_attn2<<<dim3(188, 2), 128>>>();
    k11_final<<<dim3(13, 16, 2), 64>>>(out, p2_g, p2_b);
}

// round 7
// speedup vs baseline: 2.5497x; 1.0712x over previous
#include <cuda_runtime.h>
#include <cuda_bf16.h>
#include <math.h>
#include <stdint.h>

// ---------------------------------------------------------------------------
// Static device scratch
// ---------------------------------------------------------------------------
__device__ float d_g0[5*12000];
__device__ __nv_bfloat16 d_h1h[12000*64];
__device__ __nv_bfloat16 d_h1l[12000*64];
__device__ float d_qkv1[2*6*1504*768];          // v cols = 256+o*4+m
__device__ float d_o1raw[2*2*750*128];
__device__ float d_qkv2[2*2*754*96];            // v cols = 32+o*4+m
__device__ float d_out2[2*750*16];

__device__ __nv_bfloat16 d_W1bh[768*64];
__device__ __nv_bfloat16 d_W1bl[768*64];
__device__ float d_Wcat2[128*96];
__device__ float d_Weff0[5*64];
__device__ float d_emb1[4*10];
__device__ float d_emb2[4*10];
__device__ float d_C0;

// contiguous stats block, zeroed by k0 block 16 (stream-ordered before k1):
// [0,30)=S0, [30,158)=sum1, [158,286)=sumsq1, [286,302)=sum2, [302,318)=sumsq2
__device__ float d_stats[318];
#define P_S0     (d_stats)
#define P_SUM1   (d_stats + 30)
#define P_SUMSQ1 (d_stats + 158)
#define P_SUM2   (d_stats + 286)
#define P_SUMSQ2 (d_stats + 302)

__device__ __forceinline__ void mma_bf16(float4& c,
    uint32_t a0, uint32_t a1, uint32_t a2, uint32_t a3,
    uint32_t b0, uint32_t b1)
{
    asm volatile(
        "mma.sync.aligned.m16n8k16.row.col.f32.bf16.bf16.f32 "
        "{%0,%1,%2,%3},{%4,%5,%6,%7},{%8,%9},{%0,%1,%2,%3};"
        : "+f"(c.x), "+f"(c.y), "+f"(c.z), "+f"(c.w)
        : "r"(a0), "r"(a1), "r"(a2), "r"(a3), "r"(b0), "r"(b1));
}

__device__ __forceinline__ void ldsm_x4(uint32_t& r0, uint32_t& r1, uint32_t& r2, uint32_t& r3,
                                        uint32_t addr)
{
    asm volatile("ldmatrix.sync.aligned.m8n8.x4.shared.b16 {%0,%1,%2,%3}, [%4];"
        : "=r"(r0), "=r"(r1), "=r"(r2), "=r"(r3) : "r"(addr));
}

// ---------------------------------------------------------------------------
// K0: grid 17 blocks. Blocks 0..15: weight conversion (partitioned).
//     Block 16: embeddings, Weff0, C0, stats zeroing.
// ---------------------------------------------------------------------------
__global__ void k0_pre(const float* p0_q, const float* p0_k, const float* p0_v,
                       const float* p0_ea, const float* p0_eb, const float* p0_em,
                       const float* p1_q, const float* p1_k, const float* p1_v,
                       const float* p1_ea, const float* p1_eb, const float* p1_em,
                       const float* p2_q, const float* p2_k, const float* p2_v,
                       const float* p2_ea, const float* p2_eb, const float* p2_em)
{
    int t = threadIdx.x;
    int blk = blockIdx.x;

    if (blk < 16) {
        // W1: 49152 elems, 3072 per block
        for (int u = 0; u < 12; u++) {
            int idx = blk*3072 + u*256 + t;
            int j = idx / 64, c = idx % 64;
            float v;
            if (j < 128)       v = p1_q[c*128 + j];
            else if (j < 256)  v = p1_k[c*128 + (j-128)];
            else { int o = (j-256) >> 2, m = (j-256) & 3; v = p1_v[(m*64+c)*128 + o]; }
            __nv_bfloat16 hi = __float2bfloat16_rn(v);
            d_W1bh[idx] = hi;
            d_W1bl[idx] = __float2bfloat16_rn(v - __bfloat162float(hi));
        }
        // Wcat2: 12288 elems, 768 per block
        for (int u = 0; u < 3; u++) {
            int idx = blk*768 + u*256 + t;
            int c = idx / 96, j = idx % 96;
            float v;
            if (j < 16)       v = p2_q[c*16 + j];
            else if (j < 32)  v = p2_k[c*16 + (j-16)];
            else { int o = (j-32) >> 2, m = (j-32) & 3; v = p2_v[(m*128+c)*16 + o]; }
            d_Wcat2[idx] = v;
        }
        return;
    }

    // blk == 16: zero stats + small precomputes
    for (int i = t; i < 318; i += 256) d_stats[i] = 0.f;

    __shared__ float logit0[4][5], logit1[4][10], logit2[4][10];
    __shared__ float emb0s[4][5];

    if (t == 0) {
        float s = 0.f;
        for (int o = 0; o < 64; o++) s += p0_q[o] * p0_k[o];
        d_C0 = s;
    }
    if (t >= 128 && t < 148) {
        int u = t - 128; int m = u / 5, j = u % 5;
        float la = 0.f, lb = 0.f;
        for (int o = 0; o < 64; o++) {
            la += p0_em[m*64+o] * p0_ea[o];
            lb += p0_em[m*64+o] * p0_eb[o*5+j];
        }
        logit0[m][j] = la + lb;
    }
    if (t < 40) {
        int m = t / 10, kl = t % 10, i = kl / 5, j = kl % 5;
        float la = 0.f, lb = 0.f;
        for (int o = 0; o < 128; o++) {
            la += p1_em[m*128+o] * p1_ea[o*2+i];
            lb += p1_em[m*128+o] * p1_eb[o*5+j];
        }
        logit1[m][kl] = la + lb;
    }
    if (t >= 64 && t < 104) {
        int u = t - 64; int m = u / 10, kl = u % 10, i = kl / 5, j = kl % 5;
        float la = 0.f, lb = 0.f;
        for (int o = 0; o < 16; o++) {
            la += p2_em[m*16+o] * p2_ea[o*2+i];
            lb += p2_em[m*16+o] * p2_eb[o*5+j];
        }
        logit2[m][kl] = la + lb;
    }
    __syncthreads();
    if (t < 5) {
        float mx = -1e30f;
        for (int m = 0; m < 4; m++) mx = fmaxf(mx, logit0[m][t]);
        float e[4], s = 0.f;
        for (int m = 0; m < 4; m++) { e[m] = __expf(logit0[m][t]-mx); s += e[m]; }
        for (int m = 0; m < 4; m++) emb0s[m][t] = e[m] / s;
    }
    if (t >= 32 && t < 42) {
        int kl = t - 32;
        float mx = -1e30f;
        for (int m = 0; m < 4; m++) mx = fmaxf(mx, logit1[m][kl]);
        float e[4], s = 0.f;
        for (int m = 0; m < 4; m++) { e[m] = __expf(logit1[m][kl]-mx); s += e[m]; }
        for (int m = 0; m < 4; m++) d_emb1[m*10+kl] = e[m] / s;
    }
    if (t >= 64 && t < 74) {
        int kl = t - 64;
        float mx = -1e30f;
        for (int m = 0; m < 4; m++) mx = fmaxf(mx, logit2[m][kl]);
        float e[4], s = 0.f;
        for (int m = 0; m < 4; m++) { e[m] = __expf(logit2[m][kl]-mx); s += e[m]; }
        for (int m = 0; m < 4; m++) d_emb2[m*10+kl] = e[m] / s;
    }
    __syncthreads();
    for (int idx = t; idx < 5*64; idx += blockDim.x) {
        int l = idx / 64, o = idx % 64;
        float s = 0.f;
        for (int m = 0; m < 4; m++) s += emb0s[m][l] * p0_v[m*64+o];
        d_Weff0[idx] = s;
    }
}

// ---------------------------------------------------------------------------
// K1: stage0 attention -> g[5] + low-rank BN stats. grid (24,8,2), block 128
// ---------------------------------------------------------------------------
__global__ void k1_stem0(const float* x)
{
    int tid = threadIdx.x;
    int w = blockIdx.x * 128 + tid;
    int h = blockIdx.y, b = blockIdx.z;
    bool valid = (w < 3000);

    float g[5] = {0.f,0.f,0.f,0.f,0.f};
    if (valid) {
        const float* xr = x + (b*8 + h) * 3000;
        float xc = xr[w];
        float C0 = d_C0;
        float xl[5], sc[5];
        float mx = -1e30f;
        #pragma unroll
        for (int l = 0; l < 5; l++) {
            int c = w + l - 2;
            xl[l] = (c >= 0 && c < 3000) ? xr[c] : 0.f;
            sc[l] = xc * xl[l] * C0;
            mx = fmaxf(mx, sc[l]);
        }
        float s = 0.f;
        #pragma unroll
        for (int l = 0; l < 5; l++) { sc[l] = __expf(sc[l]-mx); s += sc[l]; }
        float inv = 1.f / s;
        #pragma unroll
        for (int l = 0; l < 5; l++) g[l] = sc[l] * inv * xl[l];
    }

    float st[20];
    {
        int si = 0;
        #pragma unroll
        for (int l = 0; l < 5; l++) st[si++] = g[l];
        #pragma unroll
        for (int l = 0; l < 5; l++)
            #pragma unroll
            for (int l2 = l; l2 < 5; l2++) st[si++] = g[l]*g[l2];
    }
    #pragma unroll
    for (int i = 0; i < 20; i++)
        #pragma unroll
        for (int off = 16; off; off >>= 1)
            st[i] += __shfl_xor_sync(0xffffffffu, st[i], off);

    __shared__ float red[4][20];
    int lane = tid & 31, wrp = tid >> 5;
    if (lane == 0)
        for (int i = 0; i < 20; i++) red[wrp][i] = st[i];
    __syncthreads();
    if (tid < 20) {
        float v = red[0][tid] + red[1][tid] + red[2][tid] + red[3][tid];
        int slot;
        if (tid < 5) slot = tid;
        else {
            int k = tid - 5, l = 0;
            while (k >= 5 - l) { k -= 5 - l; l++; }
            slot = 5 + l*5 + (l + k);
        }
        atomicAdd(&P_S0[slot], v);
    }

    if (valid && !(h & 1) && !(w & 1)) {
        int p = b*6000 + (h>>1)*1500 + (w>>1);
        #pragma unroll
        for (int l = 0; l < 5; l++) d_g0[l*12000 + p] = g[l];
    }
}

// ---------------------------------------------------------------------------
// K3: stage0 BN + ReLU -> h1 bf16 hi/lo. grid 3000, block 256
// ---------------------------------------------------------------------------
__global__ void k3_h1(const float* g0, const float* b0)
{
    __shared__ float sW[5*64];
    __shared__ float sScale[64], sShift[64];
    int tid = threadIdx.x;
    for (int i = tid; i < 320; i += 256) sW[i] = d_Weff0[i];
    __syncthreads();
    if (tid < 64) {
        int c = tid;
        float Wc[5];
        #pragma unroll
        for (int l = 0; l < 5; l++) Wc[l] = sW[l*64 + c];
        float mn = 0.f, mq = 0.f;
        #pragma unroll
        for (int l = 0; l < 5; l++) {
            mn += P_S0[l] * Wc[l];
            #pragma unroll
            for (int l2 = 0; l2 < 5; l2++) {
                int lo = l < l2 ? l : l2, hi = l < l2 ? l2 : l;
                mq += P_S0[5 + lo*5 + hi] * Wc[l] * Wc[l2];
            }
        }
        float n = 48000.f;
        float mean = mn / n;
        float var  = mq / n - mean*mean;
        float sc = g0[c] * rsqrtf(var + 1e-5f);
        sScale[c] = sc;
        sShift[c] = b0[c] - mean * sc;
    }
    __syncthreads();

    int c = tid & 63;
    int p = blockIdx.x * 4 + (tid >> 6);
    float a = 0.f;
    #pragma unroll
    for (int l = 0; l < 5; l++) a += d_g0[l*12000 + p] * sW[l*64 + c];
    float y = fmaxf(fmaf(a, sScale[c], sShift[c]), 0.f);
    __nv_bfloat16 hi = __float2bfloat16_rn(y);
    d_h1h[p*64 + c] = hi;
    d_h1l[p*64 + c] = __float2bfloat16_rn(y - __bfloat162float(hi));
}

// ---------------------------------------------------------------------------
// K4: stage1 qkv GEMM (real rows only, M'=12032), bf16 3-term + ldmatrix,
// 4x2 warp layout. Zero-fills hp=0 pad rows. grid (94, 12), block 256.
// ---------------------------------------------------------------------------
#define K4_SMEM ((128*72 + 128*72 + 64*72 + 64*72) * 2)

__global__ void k4_gemm1()
{
    extern __shared__ __nv_bfloat16 sh[];
    __nv_bfloat16* Ah = sh;
    __nv_bfloat16* Al = Ah + 128*72;
    __nv_bfloat16* Bh = Al + 128*72;
    __nv_bfloat16* Bl = Bh + 64*72;

    int tid = threadIdx.x;
    int rowBase = blockIdx.x * 128;
    int colBase = blockIdx.y * 64;

    {
        int blockId = blockIdx.y * 94 + blockIdx.x;
        float4 z4 = make_float4(0.f,0.f,0.f,0.f);
        #pragma unroll
        for (int u = 0; u < 2; u++) {
            int f4idx = blockId*512 + u*256 + tid;
            int fidx = f4idx * 4;
            int row = fidx / 768, col = fidx % 768;
            int b = row >= 1504;
            int wp = row - b*1504;
            *(float4*)&d_qkv1[((size_t)b*9024 + wp)*768 + col] = z4;
        }
    }

    {
        int r = tid >> 1;
        int half = (tid & 1) * 32;
        int prow = rowBase + r;
        int b = prow / 6016; int rem = prow % 6016;
        int hp = 1 + rem / 1504; int wp = rem % 1504;
        bool valid = (wp >= 2 && wp < 1502);
        __nv_bfloat16* dh = Ah + r*72 + half;
        __nv_bfloat16* dl = Al + r*72 + half;
        if (valid) {
            int pos = ((b*4 + (hp-1))*1500 + (wp-2))*64 + half;
            const uint4* sH = (const uint4*)(d_h1h + pos);
            const uint4* sL = (const uint4*)(d_h1l + pos);
            #pragma unroll
            for (int u = 0; u < 4; u++) {
                ((uint4*)dh)[u] = sH[u];
                ((uint4*)dl)[u] = sL[u];
            }
        } else {
            uint4 z = make_uint4(0,0,0,0);
            #pragma unroll
            for (int u = 0; u < 4; u++) { ((uint4*)dh)[u] = z; ((uint4*)dl)[u] = z; }
        }
    }
    {
        int n = tid >> 2;
        int seg = (tid & 3) * 16;
        const uint4* sH = (const uint4*)(d_W1bh + (colBase + n)*64 + seg);
        const uint4* sL = (const uint4*)(d_W1bl + (colBase + n)*64 + seg);
        uint4* dh = (uint4*)(Bh + n*72 + seg);
        uint4* dl = (uint4*)(Bl + n*72 + seg);
        dh[0] = sH[0]; dh[1] = sH[1];
        dl[0] = sL[0]; dl[1] = sL[1];
    }
    __syncthreads();

    int lane = tid & 31, wid = tid >> 5;
    int g = lane >> 2, tg = lane & 3;
    int mr   = (wid >> 1) * 32;
    int ncol = (wid & 1) * 32;

    int arow = (lane < 16) ? lane : (lane - 16);
    int acol = (lane < 16) ? 0 : 8;
    uint32_t aAddrH[2], aAddrL[2];
    #pragma unroll
    for (int mt = 0; mt < 2; mt++) {
        aAddrH[mt] = (uint32_t)__cvta_generic_to_shared(Ah + (mr + mt*16 + arow)*72 + acol);
        aAddrL[mt] = (uint32_t)__cvta_generic_to_shared(Al + (mr + mt*16 + arow)*72 + acol);
    }
    int brow = (lane & 7) + ((lane >> 4) << 3);
    int bcol = ((lane >> 3) & 1) * 8;
    uint32_t bAddrH[2], bAddrL[2];
    #pragma unroll
    for (int pr = 0; pr < 2; pr++) {
        bAddrH[pr] = (uint32_t)__cvta_generic_to_shared(Bh + (ncol + pr*16 + brow)*72 + bcol);
        bAddrL[pr] = (uint32_t)__cvta_generic_to_shared(Bl + (ncol + pr*16 + brow)*72 + bcol);
    }

    float4 acc[2][4];
    #pragma unroll
    for (int i = 0; i < 2; i++)
        #pragma unroll
        for (int j = 0; j < 4; j++) acc[i][j] = make_float4(0.f,0.f,0.f,0.f);

    #pragma unroll
    for (int ks = 0; ks < 4; ks++) {
        uint32_t koff = ks * 32;
        uint32_t ah[2][4], al[2][4], bh[2][4], bl[2][4];
        #pragma unroll
        for (int mt = 0; mt < 2; mt++) {
            ldsm_x4(ah[mt][0],ah[mt][1],ah[mt][2],ah[mt][3], aAddrH[mt] + koff);
            ldsm_x4(al[mt][0],al[mt][1],al[mt][2],al[mt][3], aAddrL[mt] + koff);
        }
        #pragma unroll
        for (int pr = 0; pr < 2; pr++) {
            ldsm_x4(bh[pr][0],bh[pr][1],bh[pr][2],bh[pr][3], bAddrH[pr] + koff);
            ldsm_x4(bl[pr][0],bl[pr][1],bl[pr][2],bl[pr][3], bAddrL[pr] + koff);
        }
        #pragma unroll
        for (int mt = 0; mt < 2; mt++)
            #pragma unroll
            for (int pr = 0; pr < 2; pr++) {
                mma_bf16(acc[mt][2*pr  ], ah[mt][0],ah[mt][1],ah[mt][2],ah[mt][3], bh[pr][0],bh[pr][1]);
                mma_bf16(acc[mt][2*pr  ], ah[mt][0],ah[mt][1],ah[mt][2],ah[mt][3], bl[pr][0],bl[pr][1]);
                mma_bf16(acc[mt][2*pr  ], al[mt][0],al[mt][1],al[mt][2],al[mt][3], bh[pr][0],bh[pr][1]);
                mma_bf16(acc[mt][2*pr+1], ah[mt][0],ah[mt][1],ah[mt][2],ah[mt][3], bh[pr][2],bh[pr][3]);
                mma_bf16(acc[mt][2*pr+1], ah[mt][0],ah[mt][1],ah[mt][2],ah[mt][3], bl[pr][2],bl[pr][3]);
                mma_bf16(acc[mt][2*pr+1], al[mt][0],al[mt][1],al[mt][2],al[mt][3], bh[pr][2],bh[pr][3]);
            }
    }

    #pragma unroll
    for (int mt = 0; mt < 2; mt++) {
        #pragma unroll
        for (int half = 0; half < 2; half++) {
            int prow = rowBase + mr + mt*16 + half*8 + g;
            int b = prow / 6016; int rem = prow % 6016;
            int hp = 1 + rem / 1504; int wp = rem % 1504;
            size_t orow = (size_t)(b*6 + hp)*1504 + wp;
            #pragma unroll
            for (int j = 0; j < 4; j++) {
                int col = colBase + ncol + j*8 + tg*2;
                float2 v = half ? make_float2(acc[mt][j].z, acc[mt][j].w)
                                : make_float2(acc[mt][j].x, acc[mt][j].y);
                *(float2*)&d_qkv1[orow*768 + col] = v;
            }
        }
    }
}

// ---------------------------------------------------------------------------
// K5: stage1 attention combine with smem-staged kv window.
// 10 positions/block, 512 threads. grid (150, 4, 2).
// Dynamic smem: sq[10][128] + kv[28][640]  (floats)
// kv row r=i*14+jj holds source cols 128..767 (k then v) of (h+i, w0+jj).
// ---------------------------------------------------------------------------
#define K5_SMEM ((10*128 + 28*640) * 4)

__global__ void k5_attn1()
{
    extern __shared__ float sm5[];
    float* sq = sm5;                // [10][128]
    float* kv = sm5 + 10*128;       // [28][640]

    int w0 = blockIdx.x * 10, h = blockIdx.y, b = blockIdx.z;
    int tid = threadIdx.x, lane = tid & 31, wrp = tid >> 5;  // 16 warps
    __shared__ float ssc[10][10];
    __shared__ float cm4[10][40];

    const float* base = d_qkv1 + (size_t)b * 6 * 1504 * 768;

    // stage q rows (320 float4) and kv rows (28*160 = 4480 float4)
    for (int idx = tid; idx < 320; idx += 512) {
        int p = idx >> 5, c4 = idx & 31;
        ((float4*)sq)[p*32 + c4] =
            *(const float4*)(base + ((h+1)*1504 + (w0+2+p))*768 + c4*4);
    }
    for (int idx = tid; idx < 4480; idx += 512) {
        int r = idx / 160, c4 = idx % 160;
        int i = r / 14, jj = r % 14;
        ((float4*)(kv + r*640))[c4] =
            *(const float4*)(base + ((h+i)*1504 + (w0+jj))*768 + 128 + c4*4);
    }
    __syncthreads();

    // scores: 100 (p,kl) pairs over 16 warps (all from smem)
    for (int pair = wrp; pair < 100; pair += 16) {
        int p = pair / 10, kl = pair % 10;
        int i = kl / 5, j = kl % 5;
        float4 q4 = ((const float4*)(sq + p*128))[lane];
        float4 k4 = ((const float4*)(kv + (i*14 + p + j)*640))[lane];
        float s = q4.x*k4.x + q4.y*k4.y + q4.z*k4.z + q4.w*k4.w;
        #pragma unroll
        for (int off = 16; off; off >>= 1) s += __shfl_xor_sync(0xffffffffu, s, off);
        if (lane == 0) ssc[p][kl] = s;
    }
    __syncthreads();
    if (tid < 10) {
        float mx = -1e30f;
        #pragma unroll
        for (int kl = 0; kl < 10; kl++) mx = fmaxf(mx, ssc[tid][kl]);
        float e[10], s = 0.f;
        #pragma unroll
        for (int kl = 0; kl < 10; kl++) { e[kl] = __expf(ssc[tid][kl]-mx); s += e[kl]; }
        float inv = 1.f / s;
        #pragma unroll
        for (int kl = 0; kl < 10; kl++) {
            float a = e[kl] * inv;
            #pragma unroll
            for (int m = 0; m < 4; m++) cm4[tid][kl*4+m] = a * d_emb1[m*10+kl];
        }
    }
    __syncthreads();

    int o = tid & 127;
    int ph = tid >> 7;    // 0..3
    float s1 = 0.f, s2 = 0.f;
    for (int p = ph; p < 10; p += 4) {
        const float* cw = cm4[p];
        float acc = 0.f;
        #pragma unroll
        for (int kl = 0; kl < 10; kl++) {
            int i = kl / 5, j = kl % 5;
            float4 v = *(const float4*)(kv + (i*14 + p + j)*640 + 128 + o*4);
            acc += cw[kl*4]*v.x + cw[kl*4+1]*v.y + cw[kl*4+2]*v.z + cw[kl*4+3]*v.w;
        }
        s1 += acc; s2 += acc*acc;
        if (!(h & 1) && !((w0+p) & 1))
            d_o1raw[((b*2 + (h>>1))*750 + ((w0+p)>>1))*128 + o] = acc;
    }
    atomicAdd(&P_SUM1[o], s1);
    atomicAdd(&P_SUMSQ1[o], s2);
}

// ---------------------------------------------------------------------------
// K8: stage2 qkv GEMM, weights staged in smem, 16 positions/block.
// grid (48, 2, 2), block 384. Dynamic smem: W[128*96] + a[16][128] floats.
// ---------------------------------------------------------------------------
#define K8_SMEM ((128*96 + 16*128) * 4)

__global__ void k8_gemm2(const float* g1, const float* b1)
{
    extern __shared__ float sm8[];
    float* sWt = sm8;               // [128][96]
    float* sa  = sm8 + 128*96;      // [16][128]
    __shared__ float sScale[128], sShift[128];

    int t = threadIdx.x;
    int hp = blockIdx.y, b = blockIdx.z;
    int W0 = blockIdx.x * 16;

    if (t < 128) {
        float n = 12000.f;
        float mean = P_SUM1[t] / n;
        float var  = P_SUMSQ1[t] / n - mean*mean;
        float sc = g1[t] * rsqrtf(var + 1e-5f);
        sScale[t] = sc;
        sShift[t] = b1[t] - mean*sc;
    }
    for (int idx = t; idx < 3072; idx += 384)
        ((float4*)sWt)[idx] = ((const float4*)d_Wcat2)[idx];
    __syncthreads();

    for (int idx = t; idx < 2048; idx += 384) {
        int ps = idx >> 7, i = idx & 127;
        int wp = W0 + ps;
        float v = 0.f;
        if (wp >= 2 && wp < 752) {
            float raw = d_o1raw[(((b*2 + hp)*750) + (wp-2))*128 + i];
            v = fmaxf(fmaf(raw, sScale[i], sShift[i]), 0.f);
        }
        sa[ps*128 + i] = v;
    }
    __syncthreads();

    int grp = t / 96, o = t - grp*96;   // 4 groups x 96 outputs
    for (int ps = grp; ps < 16; ps += 4) {
        int wp = W0 + ps;
        if (wp >= 754) continue;
        const float* av = sa + ps*128;
        float acc = 0.f;
        #pragma unroll 8
        for (int c = 0; c < 128; c++) acc += av[c] * sWt[c*96 + o];
        d_qkv2[(((b*2 + hp)*754) + wp)*96 + o] = acc;
    }
}

// ---------------------------------------------------------------------------
// K9: stage2 attention combine, warp per position. grid (188, 2), block 128
// ---------------------------------------------------------------------------
__global__ void k9_attn2()
{
    __shared__ float semb[40];
    int tid = threadIdx.x;
    if (tid < 40) { int kl = tid >> 2, m = tid & 3; semb[tid] = d_emb2[m*10+kl]; }
    __syncthreads();

    int lane = tid & 31, wrp = tid >> 5;
    int w = blockIdx.x * 4 + wrp, b = blockIdx.y;
    if (w >= 750) return;

    const float* base = d_qkv2 + (size_t)b * 2 * 754 * 96;
    const float* qp = base + (w + 2) * 96;
    float qv = (lane < 16) ? qp[lane] : 0.f;

    float scl[10];
    float mx = -1e30f;
    #pragma unroll
    for (int kl = 0; kl < 10; kl++) {
        int i = kl / 5, j = kl % 5;
        const float* kp = base + (i*754 + (w+j))*96 + 16;
        float pr = (lane < 16) ? qv * kp[lane] : 0.f;
        #pragma unroll
        for (int off = 8; off; off >>= 1) pr += __shfl_xor_sync(0xffffffffu, pr, off);
        scl[kl] = pr;
        mx = fmaxf(mx, pr);
    }
    float s = 0.f;
    #pragma unroll
    for (int kl = 0; kl < 10; kl++) { scl[kl] = __expf(scl[kl]-mx); s += scl[kl]; }
    float inv = 1.f / s;
    if (lane < 16) {
        float acc = 0.f;
        #pragma unroll
        for (int kl = 0; kl < 10; kl++) {
            int i = kl / 5, j = kl % 5;
            float4 v = *(const float4*)(base + (i*754 + (w+j))*96 + 32 + lane*4);
            float aw = scl[kl] * inv;
            acc += aw * (semb[kl*4]*v.x + semb[kl*4+1]*v.y + semb[kl*4+2]*v.z + semb[kl*4+3]*v.w);
        }
        d_out2[(b*750 + w)*16 + lane] = acc;
        atomicAdd(&P_SUM2[lane], acc);
        atomicAdd(&P_SUMSQ2[lane], acc*acc);
    }
}

// ---------------------------------------------------------------------------
// K11: stage2 BN + ReLU + AvgPool(1,56) -> out. grid (13,16,2), block 64
// ---------------------------------------------------------------------------
__global__ void k11_final(float* out, const float* g2, const float* b2)
{
    int n = blockIdx.x, c = blockIdx.y, b = blockIdx.z;
    int t = threadIdx.x;
    float nn = 1500.f;
    float mean = P_SUM2[c] / nn;
    float var  = P_SUMSQ2[c] / nn - mean*mean;
    float sc = g2[c] * rsqrtf(var + 1e-5f);
    float sf = b2[c] - mean * sc;

    float v = 0.f;
    if (t < 56) {
        float raw = d_out2[(b*750 + n*56 + t)*16 + c];
        v = fmaxf(fmaf(raw, sc, sf), 0.f);
    }
    __shared__ float shm[64];
    shm[t] = v;
    __syncthreads();
    for (int st = 32; st; st >>= 1) {
        if (t < st) shm[t] += shm[t+st];
        __syncthreads();
    }
    if (t == 0) out[(b*16 + c)*13 + n] = shm[0] * (1.f/56.f);
}

// ---------------------------------------------------------------------------
extern "C" void kernel_launch(void* const* d_in, const int* in_sizes, int n_in,
                              void* d_out, int out_size)
{
    const float* x     = (const float*)d_in[0];
    const float* p0_q  = (const float*)d_in[1];
    const float* p0_k  = (const float*)d_in[2];
    const float* p0_v  = (const float*)d_in[3];
    const float* p0_ea = (const float*)d_in[4];
    const float* p0_eb = (const float*)d_in[5];
    const float* p0_em = (const float*)d_in[6];
    const float* p0_g  = (const float*)d_in[7];
    const float* p0_b  = (const float*)d_in[8];
    const float* p1_q  = (const float*)d_in[9];
    const float* p1_k  = (const float*)d_in[10];
    const float* p1_v  = (const float*)d_in[11];
    const float* p1_ea = (const float*)d_in[12];
    const float* p1_eb = (const float*)d_in[13];
    const float* p1_em = (const float*)d_in[14];
    const float* p1_g  = (const float*)d_in[15];
    const float* p1_b  = (const float*)d_in[16];
    const float* p2_q  = (const float*)d_in[17];
    const float* p2_k  = (const float*)d_in[18];
    const float* p2_v  = (const float*)d_in[19];
    const float* p2_ea = (const float*)d_in[20];
    const float* p2_eb = (const float*)d_in[21];
    const float* p2_em = (const float*)d_in[22];
    const float* p2_g  = (const float*)d_in[23];
    const float* p2_b  = (const float*)d_in[24];
    float* out = (float*)d_out;

    static int smem_set = 0;
    if (!smem_set) {
        cudaFuncSetAttribute(k4_gemm1, cudaFuncAttributeMaxDynamicSharedMemorySize, K4_SMEM);
        cudaFuncSetAttribute(k5_attn1, cudaFuncAttributeMaxDynamicSharedMemorySize, K5_SMEM);
        cudaFuncSetAttribute(k8_gemm2, cudaFuncAttributeMaxDynamicSharedMemorySize, K8_SMEM);
        smem_set = 1;
    }

    k0_pre<<<17, 256>>>(p0_q, p0_k, p0_v, p0_ea, p0_eb, p0_em,
                        p1_q, p1_k, p1_v, p1_ea, p1_eb, p1_em,
                        p2_q, p2_k, p2_v, p2_ea, p2_eb, p2_em);
    k1_stem0<<<dim3(24, 8, 2), 128>>>(x);
    k3_h1<<<3000, 256>>>(p0_g, p0_b);
    k4_gemm1<<<dim3(94, 12), 256, K4_SMEM>>>();
    k5_attn1<<<dim3(150, 4, 2), 512, K5_SMEM>>>();
    k8_gemm2<<<dim3(48, 2, 2), 384, K8_SMEM>>>(p1_g, p1_b);
    k9_attn2<<<dim3(188, 2), 128>>>();
    k11_final<<<dim3(13, 16, 2), 64>>>(out, p2_g, p2_b);
}